// round 12
// baseline (speedup 1.0000x reference)
#include <cuda_runtime.h>
#include <stdint.h>
#include <math.h>

#define B_  2
#define T_  2048
#define D_  1024
#define E_  8
#define H_  512
#define M_  2048
#define BT_ 4096
#define ST  4   // cp.async pipeline stages

// ---------------- scratch (device globals; no runtime allocation) ----------
__device__ __align__(16) float g_xr [(size_t)BT_ * D_];  // tf32-rounded x
__device__ __align__(16) float g_w1r[(size_t)H_ * D_];   // tf32-rounded sw1
__device__ __align__(16) float g_w2r[(size_t)H_ * D_];   // tf32-rounded sw2
__device__ __align__(16) float g_w3r[(size_t)D_ * H_];   // tf32-rounded sw3
__device__ __align__(16) float g_t1[(size_t)BT_ * H_];
__device__ __align__(16) float g_z [(size_t)M_  * H_];
__device__ int   g_rowi[M_];
__device__ float g_sw[M_];
__device__ float g_ew[M_];
__device__ int   g_cnt[E_];
__device__ int   g_perm[E_ * M_];
__device__ int   g_ismoe[BT_];

__device__ __forceinline__ float sigmoidf_(float v) { return 1.0f / (1.0f + expf(-v)); }

__device__ __forceinline__ float tf32r(float v) {
    unsigned u; asm("cvt.rna.tf32.f32 %0, %1;" : "=r"(u) : "f"(v));
    return __uint_as_float(u);
}
__device__ __forceinline__ unsigned tf32u(float v) {
    unsigned u; asm("cvt.rna.tf32.f32 %0, %1;" : "=r"(u) : "f"(v));
    return u;
}
#define FU(x) __float_as_uint(x)

__device__ __forceinline__ void mma8(float* c, const unsigned* a, const unsigned* b) {
    asm volatile(
        "mma.sync.aligned.m16n8k8.row.col.f32.tf32.tf32.f32 "
        "{%0,%1,%2,%3}, {%4,%5,%6,%7}, {%8,%9}, {%0,%1,%2,%3};"
        : "+f"(c[0]), "+f"(c[1]), "+f"(c[2]), "+f"(c[3])
        : "r"(a[0]), "r"(a[1]), "r"(a[2]), "r"(a[3]), "r"(b[0]), "r"(b[1]));
}

__device__ __forceinline__ void cpa16(unsigned s, const void* g) {
    asm volatile("cp.async.cg.shared.global [%0], [%1], 16;" :: "r"(s), "l"(g));
}
__device__ __forceinline__ void cp_commit() { asm volatile("cp.async.commit_group;"); }
template<int N> __device__ __forceinline__ void cp_wait() {
    asm volatile("cp.async.wait_group %0;" :: "n"(N));
}
__device__ __forceinline__ unsigned sptr(const void* p) {
    return (unsigned)__cvta_generic_to_shared(p);
}

// ---------------- K0a: round x to tf32 (+zero counters & bitmap) -----------
__global__ __launch_bounds__(256) void k_round_x(const float4* __restrict__ x4) {
    int i = blockIdx.x * 256 + threadIdx.x;
    float4 v = x4[i];
    float4 o;
    o.x = tf32r(v.x); o.y = tf32r(v.y); o.z = tf32r(v.z); o.w = tf32r(v.w);
    ((float4*)g_xr)[i] = o;
    if (blockIdx.x == 0 && threadIdx.x < E_) g_cnt[threadIdx.x] = 0;
    if (blockIdx.x < BT_ / 256) g_ismoe[blockIdx.x * 256 + threadIdx.x] = 0;
}

// ---------------- K0b: round the three shared weights -----------------------
__global__ __launch_bounds__(256) void k_round_w(
    const float4* __restrict__ w1, const float4* __restrict__ w2,
    const float4* __restrict__ w3)
{
    int i = blockIdx.x * 256 + threadIdx.x;
    float4 a = w1[i], b = w2[i], c = w3[i];
    float4 oa, ob, oc;
    oa.x = tf32r(a.x); oa.y = tf32r(a.y); oa.z = tf32r(a.z); oa.w = tf32r(a.w);
    ob.x = tf32r(b.x); ob.y = tf32r(b.y); ob.z = tf32r(b.z); ob.w = tf32r(b.w);
    oc.x = tf32r(c.x); oc.y = tf32r(c.y); oc.z = tf32r(c.z); oc.w = tf32r(c.w);
    ((float4*)g_w1r)[i] = oa;
    ((float4*)g_w2r)[i] = ob;
    ((float4*)g_w3r)[i] = oc;
}

// ---------------- K_gate: gating + expert grouping (raw x) -----------------
__global__ __launch_bounds__(256) void k_gate(
    const float* __restrict__ x,
    const int* __restrict__ ib, const int* __restrict__ it,
    const float* __restrict__ sgw, const float* __restrict__ sgb,
    const float* __restrict__ egw, const float* __restrict__ egb,
    const float* __restrict__ ebias)
{
    const int m = blockIdx.x, tid = threadIdx.x;
    const int row = ib[m] * T_ + it[m];
    const float* xr = x + (size_t)row * D_;

    float acc[9] = {};
    for (int d = tid; d < D_; d += 256) {
        float xv = xr[d];
        acc[0] = fmaf(xv, sgw[d], acc[0]);
        #pragma unroll
        for (int e = 0; e < E_; e++) acc[1+e] = fmaf(xv, egw[e*D_ + d], acc[1+e]);
    }
    #pragma unroll
    for (int q = 0; q < 9; q++)
        #pragma unroll
        for (int o = 16; o; o >>= 1) acc[q] += __shfl_xor_sync(0xffffffffu, acc[q], o);

    __shared__ float red[8][9];
    int w = tid >> 5, ln = tid & 31;
    if (!ln) {
        #pragma unroll
        for (int q = 0; q < 9; q++) red[w][q] = acc[q];
    }
    __syncthreads();
    if (tid == 0) {
        float dots[9];
        #pragma unroll
        for (int q = 0; q < 9; q++) {
            float s = 0.f;
            #pragma unroll
            for (int ww = 0; ww < 8; ww++) s += red[ww][q];
            dots[q] = s;
        }
        float ss = sigmoidf_(dots[0] + sgb[0]);
        float es[E_];
        float best = -1e30f; int bi = 0;
        #pragma unroll
        for (int e = 0; e < E_; e++) {
            es[e] = sigmoidf_(dots[1+e] + egb[e]);
            float sc = es[e] + ebias[e];
            if (sc > best) { best = sc; bi = e; }
        }
        float ts  = es[bi];
        g_rowi[m] = row;
        g_ismoe[row] = 1;
        g_sw[m] = sigmoidf_(ss - ts);
        g_ew[m] = sigmoidf_(ts - ss);
        int pos = atomicAdd(&g_cnt[bi], 1);
        g_perm[bi * M_ + pos] = m;
    }
}

// ============================================================================
// K_MLP1 (R11): fused first-layer dual GEMMs.
//   z == E_ : shared branch, BM=128 (pre-rounded weights, no cvt)
//   z  < E_ : expert branch, BM=64 (cvt weights inline)
// ============================================================================
__global__ __launch_bounds__(256) void k_mlp1(
    const float* __restrict__ b1,  const float* __restrict__ b2,
    const float* __restrict__ ew1, const float* __restrict__ eb1,
    const float* __restrict__ ew2, const float* __restrict__ eb2)
{
    __shared__ __align__(16) float As [ST][128][16];
    __shared__ __align__(16) float B1s[ST][64][16];
    __shared__ __align__(16) float B2s[ST][64][16];
    __shared__ int sM[64], sR[64];

    const int tid  = threadIdx.x;
    const int col0 = blockIdx.y * 64;
    const int wid  = tid >> 5, lane = tid & 31;
    const int grp  = lane >> 2, tig = lane & 3;
    const int wn   = (wid >> 1) * 16;
    const int lr   = tid >> 2, lc = (tid & 3) * 4;
    const int kb   = 4 * tig;
    const int NK   = D_ / 16;

    if (blockIdx.z == E_) {
        const int row0 = blockIdx.x * 128;
        const int wm   = (wid & 1) * 64;

        const float* Ag0 = g_xr  + (size_t)(row0 + lr) * D_ + lc;
        const float* Ag1 = Ag0 + (size_t)64 * D_;
        const float* B1g = g_w1r + (size_t)(col0 + lr) * D_ + lc;
        const float* B2g = g_w2r + (size_t)(col0 + lr) * D_ + lc;

        auto issue = [&](int t) {
            int s = t % ST, k0 = t * 16;
            cpa16(sptr(&As [s][lr]     [lc]), Ag0 + k0);
            cpa16(sptr(&As [s][lr + 64][lc]), Ag1 + k0);
            cpa16(sptr(&B1s[s][lr]     [lc]), B1g + k0);
            cpa16(sptr(&B2s[s][lr]     [lc]), B2g + k0);
            cp_commit();
        };

        #pragma unroll
        for (int t = 0; t < ST - 1; t++) issue(t);

        float acc1[4][2][4] = {}, acc2[4][2][4] = {};
        for (int t = 0; t < NK; t++) {
            cp_wait<ST - 2>();
            __syncthreads();
            if (t + ST - 1 < NK) issue(t + ST - 1); else cp_commit();
            const int s = t % ST;

            float4 alo[4], ahi[4], u[2], v[2];
            #pragma unroll
            for (int mi = 0; mi < 4; mi++) {
                int r0 = wm + mi * 16 + grp;
                alo[mi] = *(const float4*)&As[s][r0    ][kb];
                ahi[mi] = *(const float4*)&As[s][r0 + 8][kb];
            }
            #pragma unroll
            for (int j = 0; j < 2; j++) {
                int n = wn + j * 8 + grp;
                u[j] = *(const float4*)&B1s[s][n][kb];
                v[j] = *(const float4*)&B2s[s][n][kb];
            }
            unsigned a0[4][4], a1[4][4], bu0[2][2], bu1[2][2], bv0[2][2], bv1[2][2];
            #pragma unroll
            for (int mi = 0; mi < 4; mi++) {
                a0[mi][0] = FU(alo[mi].x); a0[mi][1] = FU(ahi[mi].x);
                a0[mi][2] = FU(alo[mi].y); a0[mi][3] = FU(ahi[mi].y);
                a1[mi][0] = FU(alo[mi].z); a1[mi][1] = FU(ahi[mi].z);
                a1[mi][2] = FU(alo[mi].w); a1[mi][3] = FU(ahi[mi].w);
            }
            #pragma unroll
            for (int j = 0; j < 2; j++) {
                bu0[j][0] = FU(u[j].x); bu0[j][1] = FU(u[j].y);
                bu1[j][0] = FU(u[j].z); bu1[j][1] = FU(u[j].w);
                bv0[j][0] = FU(v[j].x); bv0[j][1] = FU(v[j].y);
                bv1[j][0] = FU(v[j].z); bv1[j][1] = FU(v[j].w);
            }
            #pragma unroll
            for (int mi = 0; mi < 4; mi++)
                #pragma unroll
                for (int j = 0; j < 2; j++) {
                    mma8(acc1[mi][j], a0[mi], bu0[j]);
                    mma8(acc1[mi][j], a1[mi], bu1[j]);
                    mma8(acc2[mi][j], a0[mi], bv0[j]);
                    mma8(acc2[mi][j], a1[mi], bv1[j]);
                }
        }

        #pragma unroll
        for (int mi = 0; mi < 4; mi++) {
            #pragma unroll
            for (int j = 0; j < 2; j++) {
                int r = row0 + wm + mi * 16 + grp;
                int c = col0 + wn + j * 8 + 2 * tig;
                float bb1x = b1[c], bb1y = b1[c + 1];
                float bb2x = b2[c], bb2y = b2[c + 1];
                #pragma unroll
                for (int half = 0; half < 2; half++) {
                    int rr = r + half * 8;
                    float h1x = acc1[mi][j][half*2+0] + bb1x;
                    float h1y = acc1[mi][j][half*2+1] + bb1y;
                    float h2x = acc2[mi][j][half*2+0] + bb2x;
                    float h2y = acc2[mi][j][half*2+1] + bb2y;
                    float2 o;
                    o.x = h1x * sigmoidf_(h1x) * h2x;
                    o.y = h1y * sigmoidf_(h1y) * h2y;
                    *(float2*)&g_t1[(size_t)rr * H_ + c] = o;
                }
            }
        }
    } else {
        const int e = blockIdx.z;
        const int cnt = g_cnt[e];
        const int i0 = blockIdx.x * 64;
        if (i0 >= cnt) return;

        const int wm = (wid & 1) * 32;

        if (tid < 64) {
            int idx = i0 + tid; if (idx > cnt - 1) idx = cnt - 1;
            int m = g_perm[e * M_ + idx];
            sM[tid] = m; sR[tid] = g_rowi[m];
        }
        __syncthreads();

        const float* Ag  = g_xr + (size_t)sR[lr] * D_ + lc;
        const float* B1g = ew1 + (size_t)e * H_ * D_ + (size_t)(col0 + lr) * D_ + lc;
        const float* B2g = ew2 + (size_t)e * H_ * D_ + (size_t)(col0 + lr) * D_ + lc;

        auto issue = [&](int t) {
            int s = t % ST, k0 = t * 16;
            cpa16(sptr(&As [s][lr][lc]), Ag  + k0);
            cpa16(sptr(&B1s[s][lr][lc]), B1g + k0);
            cpa16(sptr(&B2s[s][lr][lc]), B2g + k0);
            cp_commit();
        };

        #pragma unroll
        for (int t = 0; t < ST - 1; t++) issue(t);

        float acc1[2][2][4] = {}, acc2[2][2][4] = {};
        for (int t = 0; t < NK; t++) {
            cp_wait<ST - 2>();
            __syncthreads();
            if (t + ST - 1 < NK) issue(t + ST - 1); else cp_commit();
            const int s = t % ST;

            unsigned a0[2][4], a1[2][4];
            #pragma unroll
            for (int mi = 0; mi < 2; mi++) {
                int r0 = wm + mi * 16 + grp;
                float4 lo = *(const float4*)&As[s][r0    ][kb];
                float4 hi = *(const float4*)&As[s][r0 + 8][kb];
                a0[mi][0] = FU(lo.x); a0[mi][1] = FU(hi.x);
                a0[mi][2] = FU(lo.y); a0[mi][3] = FU(hi.y);
                a1[mi][0] = FU(lo.z); a1[mi][1] = FU(hi.z);
                a1[mi][2] = FU(lo.w); a1[mi][3] = FU(hi.w);
            }
            unsigned bu0[2][2], bu1[2][2], bv0[2][2], bv1[2][2];
            #pragma unroll
            for (int j = 0; j < 2; j++) {
                int n = wn + j * 8 + grp;
                float4 u = *(const float4*)&B1s[s][n][kb];
                float4 v = *(const float4*)&B2s[s][n][kb];
                bu0[j][0] = tf32u(u.x); bu0[j][1] = tf32u(u.y);
                bu1[j][0] = tf32u(u.z); bu1[j][1] = tf32u(u.w);
                bv0[j][0] = tf32u(v.x); bv0[j][1] = tf32u(v.y);
                bv1[j][0] = tf32u(v.z); bv1[j][1] = tf32u(v.w);
            }
            #pragma unroll
            for (int mi = 0; mi < 2; mi++)
                #pragma unroll
                for (int j = 0; j < 2; j++) {
                    mma8(acc1[mi][j], a0[mi], bu0[j]);
                    mma8(acc1[mi][j], a1[mi], bu1[j]);
                    mma8(acc2[mi][j], a0[mi], bv0[j]);
                    mma8(acc2[mi][j], a1[mi], bv1[j]);
                }
        }

        #pragma unroll
        for (int mi = 0; mi < 2; mi++) {
            #pragma unroll
            for (int j = 0; j < 2; j++) {
                int c = col0 + wn + j * 8 + 2 * tig;
                float bb1x = eb1[e*H_ + c], bb1y = eb1[e*H_ + c + 1];
                float bb2x = eb2[e*H_ + c], bb2y = eb2[e*H_ + c + 1];
                #pragma unroll
                for (int half = 0; half < 2; half++) {
                    int li  = wm + mi * 16 + grp + half * 8;
                    int idx = i0 + li;
                    if (idx < cnt) {
                        int m = sM[li];
                        float h1x = acc1[mi][j][half*2+0] + bb1x;
                        float h1y = acc1[mi][j][half*2+1] + bb1y;
                        float h2x = acc2[mi][j][half*2+0] + bb2x;
                        float h2y = acc2[mi][j][half*2+1] + bb2y;
                        float2 o;
                        o.x = h1x * sigmoidf_(h1x) * h2x;
                        o.y = h1y * sigmoidf_(h1y) * h2y;
                        *(float2*)&g_z[(size_t)m * H_ + c] = o;
                    }
                }
            }
        }
    }
}

// ============================================================================
// K_LN: rowwise LayerNorm (width 512) for both buffers, one launch
// ============================================================================
__global__ __launch_bounds__(256) void k_ln512m(
    const float* __restrict__ g0, const float* __restrict__ b0,
    const float* __restrict__ g1, const float* __restrict__ b1)
{
    const int r = blockIdx.x;
    float* p; const float *g, *b;
    if (r < BT_) { p = g_t1 + (size_t)r * H_;         g = g0; b = b0; }
    else         { p = g_z  + (size_t)(r - BT_) * H_; g = g1; b = b1; }

    const int tid = threadIdx.x;
    float x0 = p[tid], x1 = p[tid + 256];

    __shared__ float red1[8], red2[8];
    float s = x0 + x1;
    #pragma unroll
    for (int o = 16; o; o >>= 1) s += __shfl_xor_sync(0xffffffffu, s, o);
    int w = tid >> 5, ln = tid & 31;
    if (!ln) red1[w] = s;
    __syncthreads();
    float tot = 0.f;
    #pragma unroll
    for (int i = 0; i < 8; i++) tot += red1[i];
    float mu = tot * (1.0f / (float)H_);

    float d0 = x0 - mu, d1 = x1 - mu;
    float q = d0*d0 + d1*d1;
    #pragma unroll
    for (int o = 16; o; o >>= 1) q += __shfl_xor_sync(0xffffffffu, q, o);
    if (!ln) red2[w] = q;
    __syncthreads();
    float tq = 0.f;
    #pragma unroll
    for (int i = 0; i < 8; i++) tq += red2[i];
    float rstd = rsqrtf(tq * (1.0f / (float)H_) + 1e-5f);

    p[tid]       = tf32r(d0 * rstd * g[tid]       + b[tid]);
    p[tid + 256] = tf32r(d1 * rstd * g[tid + 256] + b[tid + 256]);
}

// ============================================================================
// K_OUT: fused output stage, one launch, disjoint row writes.
//   z == E_ : shared blocks, BM=128 BN=128; write ONLY non-MoE rows:
//             out[r] = g_t1[r]@w3r^T + b3
//   z  < E_ : expert blocks, BM=64 BN=128; compute BOTH
//             acc_e = g_z[m]@ew3[e]^T  and  acc_s = g_t1[row]@w3r^T,
//             write MoE rows: out = wsh*(acc_s+b3) + wex*(acc_e+eb3)
// Dynamic smem: As/At (64x16 each) + Be/Bw (128x16 each) per stage = 96KB.
// ============================================================================
#define KOUT_SMEM (ST * (64 + 64 + 128 + 128) * 16 * 4)

__global__ __launch_bounds__(256, 2) void k_out(
    const float* __restrict__ b3,
    const float* __restrict__ ew3, const float* __restrict__ eb3,
    float* __restrict__ out)
{
    extern __shared__ __align__(16) float sm[];
    float (*As)[64][16]  = (float(*)[64][16]) sm;                        // expert: g_z | shared: A rows 0-63
    float (*At)[64][16]  = (float(*)[64][16])(sm + ST * 64 * 16);        // expert: g_t1| shared: A rows 64-127
    float (*Be)[128][16] = (float(*)[128][16])(sm + 2 * ST * 64 * 16);   // expert: ew3 | shared: w3r
    float (*Bw)[128][16] = (float(*)[128][16])(sm + 2 * ST * 64 * 16 + ST * 128 * 16); // expert: w3r

    const int tid  = threadIdx.x;
    const int wid  = tid >> 5, lane = tid & 31;
    const int grp  = lane >> 2, tig = lane & 3;
    const int wn   = (wid >> 1) * 32;
    const int lr   = tid >> 2, lc = (tid & 3) * 4;
    const int kb   = 4 * tig;
    const int col0 = blockIdx.y * 128;
    const int NK   = H_ / 16;

    if (blockIdx.z == E_) {
        // -------- shared blocks: write non-MoE rows --------
        const int row0 = blockIdx.x * 128;
        const int wm   = (wid & 1) * 64;
        float (*Ax)[64][16] = (wm == 0) ? As : At;

        const float* Ag0 = g_t1  + (size_t)(row0 + lr) * H_ + lc;
        const float* Ag1 = Ag0 + (size_t)64 * H_;
        const float* Bg0 = g_w3r + (size_t)(col0 + lr) * H_ + lc;
        const float* Bg1 = Bg0 + (size_t)64 * H_;

        auto issue = [&](int t) {
            int s = t % ST, k0 = t * 16;
            cpa16(sptr(&As[s][lr][lc]), Ag0 + k0);
            cpa16(sptr(&At[s][lr][lc]), Ag1 + k0);
            cpa16(sptr(&Be[s][lr]     [lc]), Bg0 + k0);
            cpa16(sptr(&Be[s][lr + 64][lc]), Bg1 + k0);
            cp_commit();
        };

        #pragma unroll
        for (int t = 0; t < ST - 1; t++) issue(t);

        float acc[4][4][4] = {};
        for (int t = 0; t < NK; t++) {
            cp_wait<ST - 2>();
            __syncthreads();
            if (t + ST - 1 < NK) issue(t + ST - 1); else cp_commit();
            const int s = t % ST;

            unsigned a0[4][4], a1[4][4], b0[4][2], b1[4][2];
            #pragma unroll
            for (int mi = 0; mi < 4; mi++) {
                int r0 = mi * 16 + grp;
                float4 lo = *(const float4*)&Ax[s][r0    ][kb];
                float4 hi = *(const float4*)&Ax[s][r0 + 8][kb];
                a0[mi][0] = FU(lo.x); a0[mi][1] = FU(hi.x);
                a0[mi][2] = FU(lo.y); a0[mi][3] = FU(hi.y);
                a1[mi][0] = FU(lo.z); a1[mi][1] = FU(hi.z);
                a1[mi][2] = FU(lo.w); a1[mi][3] = FU(hi.w);
            }
            #pragma unroll
            for (int j = 0; j < 4; j++) {
                float4 bq = *(const float4*)&Be[s][wn + j * 8 + grp][kb];
                b0[j][0] = FU(bq.x); b0[j][1] = FU(bq.y);
                b1[j][0] = FU(bq.z); b1[j][1] = FU(bq.w);
            }
            #pragma unroll
            for (int mi = 0; mi < 4; mi++)
                #pragma unroll
                for (int j = 0; j < 4; j++) {
                    mma8(acc[mi][j], a0[mi], b0[j]);
                    mma8(acc[mi][j], a1[mi], b1[j]);
                }
        }

        #pragma unroll
        for (int mi = 0; mi < 4; mi++) {
            #pragma unroll
            for (int half = 0; half < 2; half++) {
                int rr = row0 + wm + mi * 16 + grp + half * 8;
                if (!g_ismoe[rr]) {
                    #pragma unroll
                    for (int j = 0; j < 4; j++) {
                        int c = col0 + wn + j * 8 + 2 * tig;
                        float2 o;
                        o.x = acc[mi][j][half*2+0] + b3[c];
                        o.y = acc[mi][j][half*2+1] + b3[c + 1];
                        *(float2*)&out[(size_t)rr * D_ + c] = o;
                    }
                }
            }
        }
    } else {
        // -------- expert blocks: dual-accumulate, write MoE rows --------
        const int e = blockIdx.z;
        const int cnt = g_cnt[e];
        const int i0 = blockIdx.x * 64;
        if (i0 >= cnt) return;

        __shared__ int sM[64], sR[64];
        const int wm = (wid & 1) * 32;

        if (tid < 64) {
            int idx = i0 + tid; if (idx > cnt - 1) idx = cnt - 1;
            int m = g_perm[e * M_ + idx];
            sM[tid] = m; sR[tid] = g_rowi[m];
        }
        __syncthreads();

        const float* Agz = g_z  + (size_t)sM[lr] * H_ + lc;
        const float* Agt = g_t1 + (size_t)sR[lr] * H_ + lc;
        const float* Be0 = ew3 + (size_t)e * D_ * H_ + (size_t)(col0 + lr) * H_ + lc;
        const float* Be1 = Be0 + (size_t)64 * H_;
        const float* Bw0 = g_w3r + (size_t)(col0 + lr) * H_ + lc;
        const float* Bw1 = Bw0 + (size_t)64 * H_;

        auto issue = [&](int t) {
            int s = t % ST, k0 = t * 16;
            cpa16(sptr(&As[s][lr][lc]), Agz + k0);
            cpa16(sptr(&At[s][lr][lc]), Agt + k0);
            cpa16(sptr(&Be[s][lr]     [lc]), Be0 + k0);
            cpa16(sptr(&Be[s][lr + 64][lc]), Be1 + k0);
            cpa16(sptr(&Bw[s][lr]     [lc]), Bw0 + k0);
            cpa16(sptr(&Bw[s][lr + 64][lc]), Bw1 + k0);
            cp_commit();
        };

        #pragma unroll
        for (int t = 0; t < ST - 1; t++) issue(t);

        float acc_e[2][4][4] = {}, acc_s[2][4][4] = {};
        for (int t = 0; t < NK; t++) {
            cp_wait<ST - 2>();
            __syncthreads();
            if (t + ST - 1 < NK) issue(t + ST - 1); else cp_commit();
            const int s = t % ST;

            unsigned az0[2][4], az1[2][4], at0[2][4], at1[2][4];
            #pragma unroll
            for (int mi = 0; mi < 2; mi++) {
                int r0 = wm + mi * 16 + grp;
                float4 lo = *(const float4*)&As[s][r0    ][kb];
                float4 hi = *(const float4*)&As[s][r0 + 8][kb];
                az0[mi][0] = FU(lo.x); az0[mi][1] = FU(hi.x);
                az0[mi][2] = FU(lo.y); az0[mi][3] = FU(hi.y);
                az1[mi][0] = FU(lo.z); az1[mi][1] = FU(hi.z);
                az1[mi][2] = FU(lo.w); az1[mi][3] = FU(hi.w);
                float4 lt = *(const float4*)&At[s][r0    ][kb];
                float4 ht = *(const float4*)&At[s][r0 + 8][kb];
                at0[mi][0] = FU(lt.x); at0[mi][1] = FU(ht.x);
                at0[mi][2] = FU(lt.y); at0[mi][3] = FU(ht.y);
                at1[mi][0] = FU(lt.z); at1[mi][1] = FU(ht.z);
                at1[mi][2] = FU(lt.w); at1[mi][3] = FU(ht.w);
            }
            unsigned be0[4][2], be1[4][2], bw0[4][2], bw1[4][2];
            #pragma unroll
            for (int j = 0; j < 4; j++) {
                int n = wn + j * 8 + grp;
                float4 u = *(const float4*)&Be[s][n][kb];
                float4 v = *(const float4*)&Bw[s][n][kb];
                be0[j][0] = tf32u(u.x); be0[j][1] = tf32u(u.y);
                be1[j][0] = tf32u(u.z); be1[j][1] = tf32u(u.w);
                bw0[j][0] = FU(v.x); bw0[j][1] = FU(v.y);
                bw1[j][0] = FU(v.z); bw1[j][1] = FU(v.w);
            }
            #pragma unroll
            for (int mi = 0; mi < 2; mi++)
                #pragma unroll
                for (int j = 0; j < 4; j++) {
                    mma8(acc_e[mi][j], az0[mi], be0[j]);
                    mma8(acc_e[mi][j], az1[mi], be1[j]);
                    mma8(acc_s[mi][j], at0[mi], bw0[j]);
                    mma8(acc_s[mi][j], at1[mi], bw1[j]);
                }
        }

        #pragma unroll
        for (int mi = 0; mi < 2; mi++) {
            #pragma unroll
            for (int half = 0; half < 2; half++) {
                int li  = wm + mi * 16 + grp + half * 8;
                int idx = i0 + li;
                if (idx < cnt) {
                    int m   = sM[li];
                    int row = sR[li];
                    float wsh = g_sw[m], wex = g_ew[m];
                    #pragma unroll
                    for (int j = 0; j < 4; j++) {
                        int c = col0 + wn + j * 8 + 2 * tig;
                        float sx = acc_s[mi][j][half*2+0] + b3[c];
                        float sy = acc_s[mi][j][half*2+1] + b3[c + 1];
                        float ex = acc_e[mi][j][half*2+0] + eb3[e*D_ + c];
                        float ey = acc_e[mi][j][half*2+1] + eb3[e*D_ + c + 1];
                        float2 o;
                        o.x = wsh * sx + wex * ex;
                        o.y = wsh * sy + wex * ey;
                        *(float2*)&out[(size_t)row * D_ + c] = o;
                    }
                }
            }
        }
    }
}

// ---------------- launch ----------------------------------------------------
extern "C" void kernel_launch(void* const* d_in, const int* in_sizes, int n_in,
                              void* d_out, int out_size)
{
    const float* x      = (const float*)d_in[0];
    const int*   ib     = (const int*)  d_in[1];
    const int*   it     = (const int*)  d_in[2];
    const float* sw1    = (const float*)d_in[3];
    const float* sb1    = (const float*)d_in[4];
    const float* sw2    = (const float*)d_in[5];
    const float* sb2    = (const float*)d_in[6];
    const float* sw3    = (const float*)d_in[7];
    const float* sb3    = (const float*)d_in[8];
    const float* slng   = (const float*)d_in[9];
    const float* slnb   = (const float*)d_in[10];
    const float* sgw    = (const float*)d_in[11];
    const float* sgb    = (const float*)d_in[12];
    const float* egw    = (const float*)d_in[13];
    const float* egb    = (const float*)d_in[14];
    const float* ebias  = (const float*)d_in[15];
    const float* ew1    = (const float*)d_in[16];
    const float* eb1    = (const float*)d_in[17];
    const float* ew2    = (const float*)d_in[18];
    const float* eb2    = (const float*)d_in[19];
    const float* ew3    = (const float*)d_in[20];
    const float* eb3    = (const float*)d_in[21];
    const float* selg   = (const float*)d_in[22];
    const float* selb   = (const float*)d_in[23];
    float* out = (float*)d_out;

    static int attr_set = 0;
    if (!attr_set) {
        cudaFuncSetAttribute(k_out, cudaFuncAttributeMaxDynamicSharedMemorySize,
                             KOUT_SMEM);
        attr_set = 1;
    }

    k_round_x<<<(BT_ * D_ / 4) / 256, 256>>>((const float4*)x);
    k_round_w<<<(H_ * D_ / 4) / 256, 256>>>((const float4*)sw1,
                                            (const float4*)sw2,
                                            (const float4*)sw3);
    k_gate<<<M_, 256>>>(x, ib, it, sgw, sgb, egw, egb, ebias);
    k_mlp1<<<dim3(32, 8, E_ + 1), 256>>>(sb1, sb2, ew1, eb1, ew2, eb2);
    k_ln512m<<<BT_ + M_, 256>>>(slng, slnb, selg, selb);
    k_out<<<dim3(32, D_ / 128, E_ + 1), 256, KOUT_SMEM>>>(sb3, ew3, eb3, out);
}

// round 13
// speedup vs baseline: 1.0687x; 1.0687x over previous
#include <cuda_runtime.h>
#include <stdint.h>
#include <math.h>

#define B_  2
#define T_  2048
#define D_  1024
#define E_  8
#define H_  512
#define M_  2048
#define BT_ 4096
#define ST  4   // cp.async pipeline stages

// ---------------- scratch (device globals; no runtime allocation) ----------
__device__ __align__(16) float g_xr [(size_t)BT_ * D_];  // tf32-rounded x
__device__ __align__(16) float g_w1r[(size_t)H_ * D_];   // tf32-rounded sw1
__device__ __align__(16) float g_w2r[(size_t)H_ * D_];   // tf32-rounded sw2
__device__ __align__(16) float g_w3r[(size_t)D_ * H_];   // tf32-rounded sw3
__device__ __align__(16) float g_t1[(size_t)BT_ * H_];
__device__ __align__(16) float g_z [(size_t)M_  * H_];
__device__ int   g_rowi[M_];
__device__ float g_sw[M_];
__device__ float g_ew[M_];
__device__ int   g_cnt[E_];
__device__ int   g_perm[E_ * M_];

__device__ __forceinline__ float sigmoidf_(float v) { return 1.0f / (1.0f + expf(-v)); }

__device__ __forceinline__ float tf32r(float v) {
    unsigned u; asm("cvt.rna.tf32.f32 %0, %1;" : "=r"(u) : "f"(v));
    return __uint_as_float(u);
}
__device__ __forceinline__ unsigned tf32u(float v) {
    unsigned u; asm("cvt.rna.tf32.f32 %0, %1;" : "=r"(u) : "f"(v));
    return u;
}
#define FU(x) __float_as_uint(x)

__device__ __forceinline__ void mma8(float* c, const unsigned* a, const unsigned* b) {
    asm volatile(
        "mma.sync.aligned.m16n8k8.row.col.f32.tf32.tf32.f32 "
        "{%0,%1,%2,%3}, {%4,%5,%6,%7}, {%8,%9}, {%0,%1,%2,%3};"
        : "+f"(c[0]), "+f"(c[1]), "+f"(c[2]), "+f"(c[3])
        : "r"(a[0]), "r"(a[1]), "r"(a[2]), "r"(a[3]), "r"(b[0]), "r"(b[1]));
}

__device__ __forceinline__ void cpa16(unsigned s, const void* g) {
    asm volatile("cp.async.cg.shared.global [%0], [%1], 16;" :: "r"(s), "l"(g));
}
__device__ __forceinline__ void cp_commit() { asm volatile("cp.async.commit_group;"); }
template<int N> __device__ __forceinline__ void cp_wait() {
    asm volatile("cp.async.wait_group %0;" :: "n"(N));
}
__device__ __forceinline__ unsigned sptr(const void* p) {
    return (unsigned)__cvta_generic_to_shared(p);
}

// ---------------- K0a: round x to tf32 (+zero counters) --------------------
__global__ __launch_bounds__(256) void k_round_x(const float4* __restrict__ x4) {
    int i = blockIdx.x * 256 + threadIdx.x;
    float4 v = x4[i];
    float4 o;
    o.x = tf32r(v.x); o.y = tf32r(v.y); o.z = tf32r(v.z); o.w = tf32r(v.w);
    ((float4*)g_xr)[i] = o;
    if (blockIdx.x == 0 && threadIdx.x < E_) g_cnt[threadIdx.x] = 0;
}

// ---------------- K0b: round the three shared weights -----------------------
__global__ __launch_bounds__(256) void k_round_w(
    const float4* __restrict__ w1, const float4* __restrict__ w2,
    const float4* __restrict__ w3)
{
    int i = blockIdx.x * 256 + threadIdx.x;
    float4 a = w1[i], b = w2[i], c = w3[i];
    float4 oa, ob, oc;
    oa.x = tf32r(a.x); oa.y = tf32r(a.y); oa.z = tf32r(a.z); oa.w = tf32r(a.w);
    ob.x = tf32r(b.x); ob.y = tf32r(b.y); ob.z = tf32r(b.z); ob.w = tf32r(b.w);
    oc.x = tf32r(c.x); oc.y = tf32r(c.y); oc.z = tf32r(c.z); oc.w = tf32r(c.w);
    ((float4*)g_w1r)[i] = oa;
    ((float4*)g_w2r)[i] = ob;
    ((float4*)g_w3r)[i] = oc;
}

// ---------------- K_gate: gating + expert grouping (raw x) -----------------
__global__ __launch_bounds__(256) void k_gate(
    const float* __restrict__ x,
    const int* __restrict__ ib, const int* __restrict__ it,
    const float* __restrict__ sgw, const float* __restrict__ sgb,
    const float* __restrict__ egw, const float* __restrict__ egb,
    const float* __restrict__ ebias)
{
    const int m = blockIdx.x, tid = threadIdx.x;
    const int row = ib[m] * T_ + it[m];
    const float* xr = x + (size_t)row * D_;

    float acc[9] = {};
    for (int d = tid; d < D_; d += 256) {
        float xv = xr[d];
        acc[0] = fmaf(xv, sgw[d], acc[0]);
        #pragma unroll
        for (int e = 0; e < E_; e++) acc[1+e] = fmaf(xv, egw[e*D_ + d], acc[1+e]);
    }
    #pragma unroll
    for (int q = 0; q < 9; q++)
        #pragma unroll
        for (int o = 16; o; o >>= 1) acc[q] += __shfl_xor_sync(0xffffffffu, acc[q], o);

    __shared__ float red[8][9];
    int w = tid >> 5, ln = tid & 31;
    if (!ln) {
        #pragma unroll
        for (int q = 0; q < 9; q++) red[w][q] = acc[q];
    }
    __syncthreads();
    if (tid == 0) {
        float dots[9];
        #pragma unroll
        for (int q = 0; q < 9; q++) {
            float s = 0.f;
            #pragma unroll
            for (int ww = 0; ww < 8; ww++) s += red[ww][q];
            dots[q] = s;
        }
        float ss = sigmoidf_(dots[0] + sgb[0]);
        float es[E_];
        float best = -1e30f; int bi = 0;
        #pragma unroll
        for (int e = 0; e < E_; e++) {
            es[e] = sigmoidf_(dots[1+e] + egb[e]);
            float sc = es[e] + ebias[e];
            if (sc > best) { best = sc; bi = e; }
        }
        float ts  = es[bi];
        g_rowi[m] = row;
        g_sw[m] = sigmoidf_(ss - ts);
        g_ew[m] = sigmoidf_(ts - ss);
        int pos = atomicAdd(&g_cnt[bi], 1);
        g_perm[bi * M_ + pos] = m;
    }
}

// ============================================================================
// K_MLP1: fused first-layer dual GEMMs, phase-unrolled main loop.
//   z == E_ : shared branch, BM=128 (pre-rounded weights, no cvt)
//   z  < E_ : expert branch, BM=64 (cvt weights inline)
// ============================================================================
__global__ __launch_bounds__(256) void k_mlp1(
    const float* __restrict__ b1,  const float* __restrict__ b2,
    const float* __restrict__ ew1, const float* __restrict__ eb1,
    const float* __restrict__ ew2, const float* __restrict__ eb2)
{
    __shared__ __align__(16) float As [ST][128][16];
    __shared__ __align__(16) float B1s[ST][64][16];
    __shared__ __align__(16) float B2s[ST][64][16];
    __shared__ int sM[64], sR[64];

    const int tid  = threadIdx.x;
    const int col0 = blockIdx.y * 64;
    const int wid  = tid >> 5, lane = tid & 31;
    const int grp  = lane >> 2, tig = lane & 3;
    const int wn   = (wid >> 1) * 16;
    const int lr   = tid >> 2, lc = (tid & 3) * 4;
    const int kb   = 4 * tig;
    const int NK   = D_ / 16;   // 64, multiple of ST

    if (blockIdx.z == E_) {
        const int row0 = blockIdx.x * 128;
        const int wm   = (wid & 1) * 64;

        const float* Ag0 = g_xr  + (size_t)(row0 + lr) * D_ + lc;
        const float* Ag1 = Ag0 + (size_t)64 * D_;
        const float* B1g = g_w1r + (size_t)(col0 + lr) * D_ + lc;
        const float* B2g = g_w2r + (size_t)(col0 + lr) * D_ + lc;

        auto issue = [&](int s, int k0) {
            cpa16(sptr(&As [s][lr]     [lc]), Ag0 + k0);
            cpa16(sptr(&As [s][lr + 64][lc]), Ag1 + k0);
            cpa16(sptr(&B1s[s][lr]     [lc]), B1g + k0);
            cpa16(sptr(&B2s[s][lr]     [lc]), B2g + k0);
            cp_commit();
        };

        #pragma unroll
        for (int t = 0; t < ST - 1; t++) issue(t, t * 16);

        float acc1[4][2][4] = {}, acc2[4][2][4] = {};
        for (int t0 = 0; t0 < NK; t0 += ST) {
            #pragma unroll
            for (int u = 0; u < ST; u++) {
                const int t = t0 + u;
                cp_wait<ST - 2>();
                __syncthreads();
                if (t + ST - 1 < NK) issue((u + ST - 1) % ST, (t + ST - 1) * 16);
                else cp_commit();

                float4 alo[4], ahi[4], uu[2], vv[2];
                #pragma unroll
                for (int mi = 0; mi < 4; mi++) {
                    int r0 = wm + mi * 16 + grp;
                    alo[mi] = *(const float4*)&As[u][r0    ][kb];
                    ahi[mi] = *(const float4*)&As[u][r0 + 8][kb];
                }
                #pragma unroll
                for (int j = 0; j < 2; j++) {
                    int n = wn + j * 8 + grp;
                    uu[j] = *(const float4*)&B1s[u][n][kb];
                    vv[j] = *(const float4*)&B2s[u][n][kb];
                }
                unsigned a0[4][4], a1[4][4], bu0[2][2], bu1[2][2], bv0[2][2], bv1[2][2];
                #pragma unroll
                for (int mi = 0; mi < 4; mi++) {
                    a0[mi][0] = FU(alo[mi].x); a0[mi][1] = FU(ahi[mi].x);
                    a0[mi][2] = FU(alo[mi].y); a0[mi][3] = FU(ahi[mi].y);
                    a1[mi][0] = FU(alo[mi].z); a1[mi][1] = FU(ahi[mi].z);
                    a1[mi][2] = FU(alo[mi].w); a1[mi][3] = FU(ahi[mi].w);
                }
                #pragma unroll
                for (int j = 0; j < 2; j++) {
                    bu0[j][0] = FU(uu[j].x); bu0[j][1] = FU(uu[j].y);
                    bu1[j][0] = FU(uu[j].z); bu1[j][1] = FU(uu[j].w);
                    bv0[j][0] = FU(vv[j].x); bv0[j][1] = FU(vv[j].y);
                    bv1[j][0] = FU(vv[j].z); bv1[j][1] = FU(vv[j].w);
                }
                #pragma unroll
                for (int mi = 0; mi < 4; mi++)
                    #pragma unroll
                    for (int j = 0; j < 2; j++) {
                        mma8(acc1[mi][j], a0[mi], bu0[j]);
                        mma8(acc1[mi][j], a1[mi], bu1[j]);
                        mma8(acc2[mi][j], a0[mi], bv0[j]);
                        mma8(acc2[mi][j], a1[mi], bv1[j]);
                    }
            }
        }

        #pragma unroll
        for (int mi = 0; mi < 4; mi++) {
            #pragma unroll
            for (int j = 0; j < 2; j++) {
                int r = row0 + wm + mi * 16 + grp;
                int c = col0 + wn + j * 8 + 2 * tig;
                float bb1x = b1[c], bb1y = b1[c + 1];
                float bb2x = b2[c], bb2y = b2[c + 1];
                #pragma unroll
                for (int half = 0; half < 2; half++) {
                    int rr = r + half * 8;
                    float h1x = acc1[mi][j][half*2+0] + bb1x;
                    float h1y = acc1[mi][j][half*2+1] + bb1y;
                    float h2x = acc2[mi][j][half*2+0] + bb2x;
                    float h2y = acc2[mi][j][half*2+1] + bb2y;
                    float2 o;
                    o.x = h1x * sigmoidf_(h1x) * h2x;
                    o.y = h1y * sigmoidf_(h1y) * h2y;
                    *(float2*)&g_t1[(size_t)rr * H_ + c] = o;
                }
            }
        }
    } else {
        const int e = blockIdx.z;
        const int cnt = g_cnt[e];
        const int i0 = blockIdx.x * 64;
        if (i0 >= cnt) return;

        const int wm = (wid & 1) * 32;

        if (tid < 64) {
            int idx = i0 + tid; if (idx > cnt - 1) idx = cnt - 1;
            int m = g_perm[e * M_ + idx];
            sM[tid] = m; sR[tid] = g_rowi[m];
        }
        __syncthreads();

        const float* Ag  = g_xr + (size_t)sR[lr] * D_ + lc;
        const float* B1g = ew1 + (size_t)e * H_ * D_ + (size_t)(col0 + lr) * D_ + lc;
        const float* B2g = ew2 + (size_t)e * H_ * D_ + (size_t)(col0 + lr) * D_ + lc;

        auto issue = [&](int s, int k0) {
            cpa16(sptr(&As [s][lr][lc]), Ag  + k0);
            cpa16(sptr(&B1s[s][lr][lc]), B1g + k0);
            cpa16(sptr(&B2s[s][lr][lc]), B2g + k0);
            cp_commit();
        };

        #pragma unroll
        for (int t = 0; t < ST - 1; t++) issue(t, t * 16);

        float acc1[2][2][4] = {}, acc2[2][2][4] = {};
        for (int t0 = 0; t0 < NK; t0 += ST) {
            #pragma unroll
            for (int u = 0; u < ST; u++) {
                const int t = t0 + u;
                cp_wait<ST - 2>();
                __syncthreads();
                if (t + ST - 1 < NK) issue((u + ST - 1) % ST, (t + ST - 1) * 16);
                else cp_commit();

                unsigned a0[2][4], a1[2][4];
                #pragma unroll
                for (int mi = 0; mi < 2; mi++) {
                    int r0 = wm + mi * 16 + grp;
                    float4 lo = *(const float4*)&As[u][r0    ][kb];
                    float4 hi = *(const float4*)&As[u][r0 + 8][kb];
                    a0[mi][0] = FU(lo.x); a0[mi][1] = FU(hi.x);
                    a0[mi][2] = FU(lo.y); a0[mi][3] = FU(hi.y);
                    a1[mi][0] = FU(lo.z); a1[mi][1] = FU(hi.z);
                    a1[mi][2] = FU(lo.w); a1[mi][3] = FU(hi.w);
                }
                unsigned bu0[2][2], bu1[2][2], bv0[2][2], bv1[2][2];
                #pragma unroll
                for (int j = 0; j < 2; j++) {
                    int n = wn + j * 8 + grp;
                    float4 uu = *(const float4*)&B1s[u][n][kb];
                    float4 vv = *(const float4*)&B2s[u][n][kb];
                    bu0[j][0] = tf32u(uu.x); bu0[j][1] = tf32u(uu.y);
                    bu1[j][0] = tf32u(uu.z); bu1[j][1] = tf32u(uu.w);
                    bv0[j][0] = tf32u(vv.x); bv0[j][1] = tf32u(vv.y);
                    bv1[j][0] = tf32u(vv.z); bv1[j][1] = tf32u(vv.w);
                }
                #pragma unroll
                for (int mi = 0; mi < 2; mi++)
                    #pragma unroll
                    for (int j = 0; j < 2; j++) {
                        mma8(acc1[mi][j], a0[mi], bu0[j]);
                        mma8(acc1[mi][j], a1[mi], bu1[j]);
                        mma8(acc2[mi][j], a0[mi], bv0[j]);
                        mma8(acc2[mi][j], a1[mi], bv1[j]);
                    }
            }
        }

        #pragma unroll
        for (int mi = 0; mi < 2; mi++) {
            #pragma unroll
            for (int j = 0; j < 2; j++) {
                int c = col0 + wn + j * 8 + 2 * tig;
                float bb1x = eb1[e*H_ + c], bb1y = eb1[e*H_ + c + 1];
                float bb2x = eb2[e*H_ + c], bb2y = eb2[e*H_ + c + 1];
                #pragma unroll
                for (int half = 0; half < 2; half++) {
                    int li  = wm + mi * 16 + grp + half * 8;
                    int idx = i0 + li;
                    if (idx < cnt) {
                        int m = sM[li];
                        float h1x = acc1[mi][j][half*2+0] + bb1x;
                        float h1y = acc1[mi][j][half*2+1] + bb1y;
                        float h2x = acc2[mi][j][half*2+0] + bb2x;
                        float h2y = acc2[mi][j][half*2+1] + bb2y;
                        float2 o;
                        o.x = h1x * sigmoidf_(h1x) * h2x;
                        o.y = h1y * sigmoidf_(h1y) * h2y;
                        *(float2*)&g_z[(size_t)m * H_ + c] = o;
                    }
                }
            }
        }
    }
}

// ============================================================================
// K_LN: rowwise LayerNorm (width 512) for both buffers, one launch
// ============================================================================
__global__ __launch_bounds__(256) void k_ln512m(
    const float* __restrict__ g0, const float* __restrict__ b0,
    const float* __restrict__ g1, const float* __restrict__ b1)
{
    const int r = blockIdx.x;
    float* p; const float *g, *b;
    if (r < BT_) { p = g_t1 + (size_t)r * H_;         g = g0; b = b0; }
    else         { p = g_z  + (size_t)(r - BT_) * H_; g = g1; b = b1; }

    const int tid = threadIdx.x;
    float x0 = p[tid], x1 = p[tid + 256];

    __shared__ float red1[8], red2[8];
    float s = x0 + x1;
    #pragma unroll
    for (int o = 16; o; o >>= 1) s += __shfl_xor_sync(0xffffffffu, s, o);
    int w = tid >> 5, ln = tid & 31;
    if (!ln) red1[w] = s;
    __syncthreads();
    float tot = 0.f;
    #pragma unroll
    for (int i = 0; i < 8; i++) tot += red1[i];
    float mu = tot * (1.0f / (float)H_);

    float d0 = x0 - mu, d1 = x1 - mu;
    float q = d0*d0 + d1*d1;
    #pragma unroll
    for (int o = 16; o; o >>= 1) q += __shfl_xor_sync(0xffffffffu, q, o);
    if (!ln) red2[w] = q;
    __syncthreads();
    float tq = 0.f;
    #pragma unroll
    for (int i = 0; i < 8; i++) tq += red2[i];
    float rstd = rsqrtf(tq * (1.0f / (float)H_) + 1e-5f);

    p[tid]       = tf32r(d0 * rstd * g[tid]       + b[tid]);
    p[tid + 256] = tf32r(d1 * rstd * g[tid + 256] + b[tid + 256]);
}

// ============================================================================
// K3: shared_out = sh @ w3r^T + sb3 -> d_out (both operands pre-rounded)
// BM=128 BN=128 BK=16, warps 2x4, phase-unrolled
// ============================================================================
__global__ __launch_bounds__(256) void k_shared_out(
    const float* __restrict__ b3, float* __restrict__ out)
{
    __shared__ __align__(16) float As[ST][128][16];
    __shared__ __align__(16) float Bs[ST][128][16];

    const int tid  = threadIdx.x;
    const int row0 = blockIdx.x * 128;
    const int col0 = blockIdx.y * 128;
    const int wid  = tid >> 5, lane = tid & 31;
    const int grp  = lane >> 2, tig = lane & 3;
    const int wm   = (wid & 1) * 64;
    const int wn   = (wid >> 1) * 32;
    const int lr   = tid >> 2, lc = (tid & 3) * 4;
    const int kb   = 4 * tig;

    const float* Ag0 = g_t1  + (size_t)(row0 + lr) * H_ + lc;
    const float* Ag1 = Ag0 + (size_t)64 * H_;
    const float* Bg0 = g_w3r + (size_t)(col0 + lr) * H_ + lc;
    const float* Bg1 = Bg0 + (size_t)64 * H_;

    auto issue = [&](int s, int k0) {
        cpa16(sptr(&As[s][lr]     [lc]), Ag0 + k0);
        cpa16(sptr(&As[s][lr + 64][lc]), Ag1 + k0);
        cpa16(sptr(&Bs[s][lr]     [lc]), Bg0 + k0);
        cpa16(sptr(&Bs[s][lr + 64][lc]), Bg1 + k0);
        cp_commit();
    };

    const int NK = H_ / 16;   // 32, multiple of ST
    #pragma unroll
    for (int t = 0; t < ST - 1; t++) issue(t, t * 16);

    float acc[4][4][4] = {};
    for (int t0 = 0; t0 < NK; t0 += ST) {
        #pragma unroll
        for (int u = 0; u < ST; u++) {
            const int t = t0 + u;
            cp_wait<ST - 2>();
            __syncthreads();
            if (t + ST - 1 < NK) issue((u + ST - 1) % ST, (t + ST - 1) * 16);
            else cp_commit();

            float4 alo[4], ahi[4], bq[4];
            #pragma unroll
            for (int mi = 0; mi < 4; mi++) {
                int r0 = wm + mi * 16 + grp;
                alo[mi] = *(const float4*)&As[u][r0    ][kb];
                ahi[mi] = *(const float4*)&As[u][r0 + 8][kb];
            }
            #pragma unroll
            for (int j = 0; j < 4; j++)
                bq[j] = *(const float4*)&Bs[u][wn + j * 8 + grp][kb];

            unsigned a0[4][4], a1[4][4], b0[4][2], b1[4][2];
            #pragma unroll
            for (int mi = 0; mi < 4; mi++) {
                a0[mi][0] = FU(alo[mi].x); a0[mi][1] = FU(ahi[mi].x);
                a0[mi][2] = FU(alo[mi].y); a0[mi][3] = FU(ahi[mi].y);
                a1[mi][0] = FU(alo[mi].z); a1[mi][1] = FU(ahi[mi].z);
                a1[mi][2] = FU(alo[mi].w); a1[mi][3] = FU(ahi[mi].w);
            }
            #pragma unroll
            for (int j = 0; j < 4; j++) {
                b0[j][0] = FU(bq[j].x); b0[j][1] = FU(bq[j].y);
                b1[j][0] = FU(bq[j].z); b1[j][1] = FU(bq[j].w);
            }
            #pragma unroll
            for (int mi = 0; mi < 4; mi++)
                #pragma unroll
                for (int j = 0; j < 4; j++) {
                    mma8(acc[mi][j], a0[mi], b0[j]);
                    mma8(acc[mi][j], a1[mi], b1[j]);
                }
        }
    }

    #pragma unroll
    for (int mi = 0; mi < 4; mi++) {
        #pragma unroll
        for (int j = 0; j < 4; j++) {
            int r = row0 + wm + mi * 16 + grp;
            int c = col0 + wn + j * 8 + 2 * tig;
            float bx = b3[c], by = b3[c + 1];
            #pragma unroll
            for (int half = 0; half < 2; half++) {
                int rr = r + half * 8;
                float2 o;
                o.x = acc[mi][j][half*2+0] + bx;
                o.y = acc[mi][j][half*2+1] + by;
                *(float2*)&out[(size_t)rr * D_ + c] = o;
            }
        }
    }
}

// ============================================================================
// K7: expert out GEMM + weighted combine   BM=64 BN=128, phase-unrolled
// ============================================================================
__global__ __launch_bounds__(256) void k_expert_out(
    const float* __restrict__ ew3, const float* __restrict__ eb3,
    float* __restrict__ out)
{
    const int e = blockIdx.z;
    const int cnt = g_cnt[e];
    const int i0 = blockIdx.x * 64;
    if (i0 >= cnt) return;

    __shared__ int sM[64];
    __shared__ __align__(16) float As[ST][64][16];
    __shared__ __align__(16) float Bs[ST][128][16];

    const int col0 = blockIdx.y * 128;
    const int tid  = threadIdx.x;
    const int wid  = tid >> 5, lane = tid & 31;
    const int grp  = lane >> 2, tig = lane & 3;
    const int wm   = (wid & 1) * 32;
    const int wn   = (wid >> 1) * 32;
    const int lr   = tid >> 2, lc = (tid & 3) * 4;
    const int kb   = 4 * tig;

    if (tid < 64) {
        int idx = i0 + tid; if (idx > cnt - 1) idx = cnt - 1;
        sM[tid] = g_perm[e * M_ + idx];
    }
    __syncthreads();

    const float* Ag  = g_z + (size_t)sM[lr] * H_ + lc;
    const float* Bg0 = ew3 + (size_t)e * D_ * H_ + (size_t)(col0 + lr) * H_ + lc;
    const float* Bg1 = Bg0 + (size_t)64 * H_;

    auto issue = [&](int s, int k0) {
        cpa16(sptr(&As[s][lr]     [lc]), Ag  + k0);
        cpa16(sptr(&Bs[s][lr]     [lc]), Bg0 + k0);
        cpa16(sptr(&Bs[s][lr + 64][lc]), Bg1 + k0);
        cp_commit();
    };

    const int NK = H_ / 16;   // 32
    #pragma unroll
    for (int t = 0; t < ST - 1; t++) issue(t, t * 16);

    float acc[2][4][4] = {};
    for (int t0 = 0; t0 < NK; t0 += ST) {
        #pragma unroll
        for (int u = 0; u < ST; u++) {
            const int t = t0 + u;
            cp_wait<ST - 2>();
            __syncthreads();
            if (t + ST - 1 < NK) issue((u + ST - 1) % ST, (t + ST - 1) * 16);
            else cp_commit();

            unsigned a0[2][4], a1[2][4];
            #pragma unroll
            for (int mi = 0; mi < 2; mi++) {
                int r0 = wm + mi * 16 + grp;
                float4 lo = *(const float4*)&As[u][r0    ][kb];
                float4 hi = *(const float4*)&As[u][r0 + 8][kb];
                a0[mi][0] = FU(lo.x); a0[mi][1] = FU(hi.x);
                a0[mi][2] = FU(lo.y); a0[mi][3] = FU(hi.y);
                a1[mi][0] = FU(lo.z); a1[mi][1] = FU(hi.z);
                a1[mi][2] = FU(lo.w); a1[mi][3] = FU(hi.w);
            }
            unsigned b0[4][2], b1[4][2];
            #pragma unroll
            for (int j = 0; j < 4; j++) {
                float4 bq = *(const float4*)&Bs[u][wn + j * 8 + grp][kb];
                b0[j][0] = tf32u(bq.x); b0[j][1] = tf32u(bq.y);
                b1[j][0] = tf32u(bq.z); b1[j][1] = tf32u(bq.w);
            }
            #pragma unroll
            for (int mi = 0; mi < 2; mi++)
                #pragma unroll
                for (int j = 0; j < 4; j++) {
                    mma8(acc[mi][j], a0[mi], b0[j]);
                    mma8(acc[mi][j], a1[mi], b1[j]);
                }
        }
    }

    #pragma unroll
    for (int mi = 0; mi < 2; mi++) {
        #pragma unroll
        for (int half = 0; half < 2; half++) {
            int li  = wm + mi * 16 + grp + half * 8;
            int idx = i0 + li;
            if (idx < cnt) {
                int m   = sM[li];
                int row = g_rowi[m];
                float wsh = g_sw[m], wex = g_ew[m];
                #pragma unroll
                for (int j = 0; j < 4; j++) {
                    int c = col0 + wn + j * 8 + 2 * tig;
                    float vx = acc[mi][j][half*2+0] + eb3[e*D_ + c];
                    float vy = acc[mi][j][half*2+1] + eb3[e*D_ + c + 1];
                    size_t o = (size_t)row * D_ + c;
                    float2 cur = *(float2*)&out[o];
                    float2 nv;
                    nv.x = wsh * cur.x + wex * vx;
                    nv.y = wsh * cur.y + wex * vy;
                    *(float2*)&out[o] = nv;
                }
            }
        }
    }
}

// ---------------- launch ----------------------------------------------------
extern "C" void kernel_launch(void* const* d_in, const int* in_sizes, int n_in,
                              void* d_out, int out_size)
{
    const float* x      = (const float*)d_in[0];
    const int*   ib     = (const int*)  d_in[1];
    const int*   it     = (const int*)  d_in[2];
    const float* sw1    = (const float*)d_in[3];
    const float* sb1    = (const float*)d_in[4];
    const float* sw2    = (const float*)d_in[5];
    const float* sb2    = (const float*)d_in[6];
    const float* sw3    = (const float*)d_in[7];
    const float* sb3    = (const float*)d_in[8];
    const float* slng   = (const float*)d_in[9];
    const float* slnb   = (const float*)d_in[10];
    const float* sgw    = (const float*)d_in[11];
    const float* sgb    = (const float*)d_in[12];
    const float* egw    = (const float*)d_in[13];
    const float* egb    = (const float*)d_in[14];
    const float* ebias  = (const float*)d_in[15];
    const float* ew1    = (const float*)d_in[16];
    const float* eb1    = (const float*)d_in[17];
    const float* ew2    = (const float*)d_in[18];
    const float* eb2    = (const float*)d_in[19];
    const float* ew3    = (const float*)d_in[20];
    const float* eb3    = (const float*)d_in[21];
    const float* selg   = (const float*)d_in[22];
    const float* selb   = (const float*)d_in[23];
    float* out = (float*)d_out;

    k_round_x<<<(BT_ * D_ / 4) / 256, 256>>>((const float4*)x);
    k_round_w<<<(H_ * D_ / 4) / 256, 256>>>((const float4*)sw1,
                                            (const float4*)sw2,
                                            (const float4*)sw3);
    k_gate<<<M_, 256>>>(x, ib, it, sgw, sgb, egw, egb, ebias);
    k_mlp1<<<dim3(32, 8, E_ + 1), 256>>>(sb1, sb2, ew1, eb1, ew2, eb2);
    k_ln512m<<<BT_ + M_, 256>>>(slng, slnb, selg, selb);
    k_shared_out<<<dim3(BT_/128, D_/128), 256>>>(sb3, out);
    k_expert_out<<<dim3(M_/64, D_/128, E_), 256>>>(ew3, eb3, out);
}

// round 14
// speedup vs baseline: 1.1005x; 1.0297x over previous
#include <cuda_runtime.h>
#include <stdint.h>
#include <math.h>

#define B_  2
#define T_  2048
#define D_  1024
#define E_  8
#define H_  512
#define M_  2048
#define BT_ 4096
#define ST  4   // cp.async pipeline stages

// ---------------- scratch (device globals; no runtime allocation) ----------
__device__ __align__(16) float g_xr [(size_t)BT_ * D_];  // tf32-rounded x
__device__ __align__(16) float g_w1r[(size_t)H_ * D_];   // tf32-rounded sw1
__device__ __align__(16) float g_w2r[(size_t)H_ * D_];   // tf32-rounded sw2
__device__ __align__(16) float g_w3r[(size_t)D_ * H_];   // tf32-rounded sw3
__device__ __align__(16) float g_t1[(size_t)BT_ * H_];
__device__ __align__(16) float g_z [(size_t)M_  * H_];
__device__ __align__(16) float g_eo[(size_t)M_  * D_];   // expert out (pre-combine)
__device__ int   g_rowi[M_];
__device__ float g_sw[M_];
__device__ float g_ew[M_];
__device__ int   g_cnt[E_];
__device__ int   g_perm[E_ * M_];

__device__ __forceinline__ float sigmoidf_(float v) { return 1.0f / (1.0f + expf(-v)); }

__device__ __forceinline__ float tf32r(float v) {
    unsigned u; asm("cvt.rna.tf32.f32 %0, %1;" : "=r"(u) : "f"(v));
    return __uint_as_float(u);
}
__device__ __forceinline__ unsigned tf32u(float v) {
    unsigned u; asm("cvt.rna.tf32.f32 %0, %1;" : "=r"(u) : "f"(v));
    return u;
}
#define FU(x) __float_as_uint(x)

__device__ __forceinline__ void mma8(float* c, const unsigned* a, const unsigned* b) {
    asm volatile(
        "mma.sync.aligned.m16n8k8.row.col.f32.tf32.tf32.f32 "
        "{%0,%1,%2,%3}, {%4,%5,%6,%7}, {%8,%9}, {%0,%1,%2,%3};"
        : "+f"(c[0]), "+f"(c[1]), "+f"(c[2]), "+f"(c[3])
        : "r"(a[0]), "r"(a[1]), "r"(a[2]), "r"(a[3]), "r"(b[0]), "r"(b[1]));
}

__device__ __forceinline__ void cpa16(unsigned s, const void* g) {
    asm volatile("cp.async.cg.shared.global [%0], [%1], 16;" :: "r"(s), "l"(g));
}
__device__ __forceinline__ void cp_commit() { asm volatile("cp.async.commit_group;"); }
template<int N> __device__ __forceinline__ void cp_wait() {
    asm volatile("cp.async.wait_group %0;" :: "n"(N));
}
__device__ __forceinline__ unsigned sptr(const void* p) {
    return (unsigned)__cvta_generic_to_shared(p);
}

// ---------------- K0: round x + shared weights (+zero counters), one launch -
// blocks [0, 4096)        -> x (BT*D/4 float4)
// blocks [4096, 4608)     -> w1/w2/w3 (H*D/4 float4 each)
__global__ __launch_bounds__(256) void k_round_all(
    const float4* __restrict__ x4,
    const float4* __restrict__ w1, const float4* __restrict__ w2,
    const float4* __restrict__ w3)
{
    const int bx = blockIdx.x;
    if (bx < (BT_ * D_ / 4) / 256) {
        int i = bx * 256 + threadIdx.x;
        float4 v = x4[i];
        float4 o;
        o.x = tf32r(v.x); o.y = tf32r(v.y); o.z = tf32r(v.z); o.w = tf32r(v.w);
        ((float4*)g_xr)[i] = o;
        if (bx == 0 && threadIdx.x < E_) g_cnt[threadIdx.x] = 0;
    } else {
        int i = (bx - (BT_ * D_ / 4) / 256) * 256 + threadIdx.x;
        float4 a = w1[i], b = w2[i], c = w3[i];
        float4 oa, ob, oc;
        oa.x = tf32r(a.x); oa.y = tf32r(a.y); oa.z = tf32r(a.z); oa.w = tf32r(a.w);
        ob.x = tf32r(b.x); ob.y = tf32r(b.y); ob.z = tf32r(b.z); ob.w = tf32r(b.w);
        oc.x = tf32r(c.x); oc.y = tf32r(c.y); oc.z = tf32r(c.z); oc.w = tf32r(c.w);
        ((float4*)g_w1r)[i] = oa;
        ((float4*)g_w2r)[i] = ob;
        ((float4*)g_w3r)[i] = oc;
    }
}

// ---------------- K_gate: gating + expert grouping (raw x) -----------------
__global__ __launch_bounds__(256) void k_gate(
    const float* __restrict__ x,
    const int* __restrict__ ib, const int* __restrict__ it,
    const float* __restrict__ sgw, const float* __restrict__ sgb,
    const float* __restrict__ egw, const float* __restrict__ egb,
    const float* __restrict__ ebias)
{
    const int m = blockIdx.x, tid = threadIdx.x;
    const int row = ib[m] * T_ + it[m];
    const float* xr = x + (size_t)row * D_;

    float acc[9] = {};
    for (int d = tid; d < D_; d += 256) {
        float xv = xr[d];
        acc[0] = fmaf(xv, sgw[d], acc[0]);
        #pragma unroll
        for (int e = 0; e < E_; e++) acc[1+e] = fmaf(xv, egw[e*D_ + d], acc[1+e]);
    }
    #pragma unroll
    for (int q = 0; q < 9; q++)
        #pragma unroll
        for (int o = 16; o; o >>= 1) acc[q] += __shfl_xor_sync(0xffffffffu, acc[q], o);

    __shared__ float red[8][9];
    int w = tid >> 5, ln = tid & 31;
    if (!ln) {
        #pragma unroll
        for (int q = 0; q < 9; q++) red[w][q] = acc[q];
    }
    __syncthreads();
    if (tid == 0) {
        float dots[9];
        #pragma unroll
        for (int q = 0; q < 9; q++) {
            float s = 0.f;
            #pragma unroll
            for (int ww = 0; ww < 8; ww++) s += red[ww][q];
            dots[q] = s;
        }
        float ss = sigmoidf_(dots[0] + sgb[0]);
        float es[E_];
        float best = -1e30f; int bi = 0;
        #pragma unroll
        for (int e = 0; e < E_; e++) {
            es[e] = sigmoidf_(dots[1+e] + egb[e]);
            float sc = es[e] + ebias[e];
            if (sc > best) { best = sc; bi = e; }
        }
        float ts  = es[bi];
        g_rowi[m] = row;
        g_sw[m] = sigmoidf_(ss - ts);
        g_ew[m] = sigmoidf_(ts - ss);
        int pos = atomicAdd(&g_cnt[bi], 1);
        g_perm[bi * M_ + pos] = m;
    }
}

// ============================================================================
// K_MLP1: fused first-layer dual GEMMs, phase-unrolled main loop.
//   z == E_ : shared branch, BM=128 (pre-rounded weights, no cvt)
//   z  < E_ : expert branch, BM=64 (cvt weights inline)
// ============================================================================
__global__ __launch_bounds__(256) void k_mlp1(
    const float* __restrict__ b1,  const float* __restrict__ b2,
    const float* __restrict__ ew1, const float* __restrict__ eb1,
    const float* __restrict__ ew2, const float* __restrict__ eb2)
{
    __shared__ __align__(16) float As [ST][128][16];
    __shared__ __align__(16) float B1s[ST][64][16];
    __shared__ __align__(16) float B2s[ST][64][16];
    __shared__ int sM[64], sR[64];

    const int tid  = threadIdx.x;
    const int col0 = blockIdx.y * 64;
    const int wid  = tid >> 5, lane = tid & 31;
    const int grp  = lane >> 2, tig = lane & 3;
    const int wn   = (wid >> 1) * 16;
    const int lr   = tid >> 2, lc = (tid & 3) * 4;
    const int kb   = 4 * tig;
    const int NK   = D_ / 16;   // 64, multiple of ST

    if (blockIdx.z == E_) {
        const int row0 = blockIdx.x * 128;
        const int wm   = (wid & 1) * 64;

        const float* Ag0 = g_xr  + (size_t)(row0 + lr) * D_ + lc;
        const float* Ag1 = Ag0 + (size_t)64 * D_;
        const float* B1g = g_w1r + (size_t)(col0 + lr) * D_ + lc;
        const float* B2g = g_w2r + (size_t)(col0 + lr) * D_ + lc;

        auto issue = [&](int s, int k0) {
            cpa16(sptr(&As [s][lr]     [lc]), Ag0 + k0);
            cpa16(sptr(&As [s][lr + 64][lc]), Ag1 + k0);
            cpa16(sptr(&B1s[s][lr]     [lc]), B1g + k0);
            cpa16(sptr(&B2s[s][lr]     [lc]), B2g + k0);
            cp_commit();
        };

        #pragma unroll
        for (int t = 0; t < ST - 1; t++) issue(t, t * 16);

        float acc1[4][2][4] = {}, acc2[4][2][4] = {};
        for (int t0 = 0; t0 < NK; t0 += ST) {
            #pragma unroll
            for (int u = 0; u < ST; u++) {
                const int t = t0 + u;
                cp_wait<ST - 2>();
                __syncthreads();
                if (t + ST - 1 < NK) issue((u + ST - 1) % ST, (t + ST - 1) * 16);
                else cp_commit();

                float4 alo[4], ahi[4], uu[2], vv[2];
                #pragma unroll
                for (int mi = 0; mi < 4; mi++) {
                    int r0 = wm + mi * 16 + grp;
                    alo[mi] = *(const float4*)&As[u][r0    ][kb];
                    ahi[mi] = *(const float4*)&As[u][r0 + 8][kb];
                }
                #pragma unroll
                for (int j = 0; j < 2; j++) {
                    int n = wn + j * 8 + grp;
                    uu[j] = *(const float4*)&B1s[u][n][kb];
                    vv[j] = *(const float4*)&B2s[u][n][kb];
                }
                unsigned a0[4][4], a1[4][4], bu0[2][2], bu1[2][2], bv0[2][2], bv1[2][2];
                #pragma unroll
                for (int mi = 0; mi < 4; mi++) {
                    a0[mi][0] = FU(alo[mi].x); a0[mi][1] = FU(ahi[mi].x);
                    a0[mi][2] = FU(alo[mi].y); a0[mi][3] = FU(ahi[mi].y);
                    a1[mi][0] = FU(alo[mi].z); a1[mi][1] = FU(ahi[mi].z);
                    a1[mi][2] = FU(alo[mi].w); a1[mi][3] = FU(ahi[mi].w);
                }
                #pragma unroll
                for (int j = 0; j < 2; j++) {
                    bu0[j][0] = FU(uu[j].x); bu0[j][1] = FU(uu[j].y);
                    bu1[j][0] = FU(uu[j].z); bu1[j][1] = FU(uu[j].w);
                    bv0[j][0] = FU(vv[j].x); bv0[j][1] = FU(vv[j].y);
                    bv1[j][0] = FU(vv[j].z); bv1[j][1] = FU(vv[j].w);
                }
                #pragma unroll
                for (int mi = 0; mi < 4; mi++)
                    #pragma unroll
                    for (int j = 0; j < 2; j++) {
                        mma8(acc1[mi][j], a0[mi], bu0[j]);
                        mma8(acc1[mi][j], a1[mi], bu1[j]);
                        mma8(acc2[mi][j], a0[mi], bv0[j]);
                        mma8(acc2[mi][j], a1[mi], bv1[j]);
                    }
            }
        }

        #pragma unroll
        for (int mi = 0; mi < 4; mi++) {
            #pragma unroll
            for (int j = 0; j < 2; j++) {
                int r = row0 + wm + mi * 16 + grp;
                int c = col0 + wn + j * 8 + 2 * tig;
                float bb1x = b1[c], bb1y = b1[c + 1];
                float bb2x = b2[c], bb2y = b2[c + 1];
                #pragma unroll
                for (int half = 0; half < 2; half++) {
                    int rr = r + half * 8;
                    float h1x = acc1[mi][j][half*2+0] + bb1x;
                    float h1y = acc1[mi][j][half*2+1] + bb1y;
                    float h2x = acc2[mi][j][half*2+0] + bb2x;
                    float h2y = acc2[mi][j][half*2+1] + bb2y;
                    float2 o;
                    o.x = h1x * sigmoidf_(h1x) * h2x;
                    o.y = h1y * sigmoidf_(h1y) * h2y;
                    *(float2*)&g_t1[(size_t)rr * H_ + c] = o;
                }
            }
        }
    } else {
        const int e = blockIdx.z;
        const int cnt = g_cnt[e];
        const int i0 = blockIdx.x * 64;
        if (i0 >= cnt) return;

        const int wm = (wid & 1) * 32;

        if (tid < 64) {
            int idx = i0 + tid; if (idx > cnt - 1) idx = cnt - 1;
            int m = g_perm[e * M_ + idx];
            sM[tid] = m; sR[tid] = g_rowi[m];
        }
        __syncthreads();

        const float* Ag  = g_xr + (size_t)sR[lr] * D_ + lc;
        const float* B1g = ew1 + (size_t)e * H_ * D_ + (size_t)(col0 + lr) * D_ + lc;
        const float* B2g = ew2 + (size_t)e * H_ * D_ + (size_t)(col0 + lr) * D_ + lc;

        auto issue = [&](int s, int k0) {
            cpa16(sptr(&As [s][lr][lc]), Ag  + k0);
            cpa16(sptr(&B1s[s][lr][lc]), B1g + k0);
            cpa16(sptr(&B2s[s][lr][lc]), B2g + k0);
            cp_commit();
        };

        #pragma unroll
        for (int t = 0; t < ST - 1; t++) issue(t, t * 16);

        float acc1[2][2][4] = {}, acc2[2][2][4] = {};
        for (int t0 = 0; t0 < NK; t0 += ST) {
            #pragma unroll
            for (int u = 0; u < ST; u++) {
                const int t = t0 + u;
                cp_wait<ST - 2>();
                __syncthreads();
                if (t + ST - 1 < NK) issue((u + ST - 1) % ST, (t + ST - 1) * 16);
                else cp_commit();

                unsigned a0[2][4], a1[2][4];
                #pragma unroll
                for (int mi = 0; mi < 2; mi++) {
                    int r0 = wm + mi * 16 + grp;
                    float4 lo = *(const float4*)&As[u][r0    ][kb];
                    float4 hi = *(const float4*)&As[u][r0 + 8][kb];
                    a0[mi][0] = FU(lo.x); a0[mi][1] = FU(hi.x);
                    a0[mi][2] = FU(lo.y); a0[mi][3] = FU(hi.y);
                    a1[mi][0] = FU(lo.z); a1[mi][1] = FU(hi.z);
                    a1[mi][2] = FU(lo.w); a1[mi][3] = FU(hi.w);
                }
                unsigned bu0[2][2], bu1[2][2], bv0[2][2], bv1[2][2];
                #pragma unroll
                for (int j = 0; j < 2; j++) {
                    int n = wn + j * 8 + grp;
                    float4 uu = *(const float4*)&B1s[u][n][kb];
                    float4 vv = *(const float4*)&B2s[u][n][kb];
                    bu0[j][0] = tf32u(uu.x); bu0[j][1] = tf32u(uu.y);
                    bu1[j][0] = tf32u(uu.z); bu1[j][1] = tf32u(uu.w);
                    bv0[j][0] = tf32u(vv.x); bv0[j][1] = tf32u(vv.y);
                    bv1[j][0] = tf32u(vv.z); bv1[j][1] = tf32u(vv.w);
                }
                #pragma unroll
                for (int mi = 0; mi < 2; mi++)
                    #pragma unroll
                    for (int j = 0; j < 2; j++) {
                        mma8(acc1[mi][j], a0[mi], bu0[j]);
                        mma8(acc1[mi][j], a1[mi], bu1[j]);
                        mma8(acc2[mi][j], a0[mi], bv0[j]);
                        mma8(acc2[mi][j], a1[mi], bv1[j]);
                    }
            }
        }

        #pragma unroll
        for (int mi = 0; mi < 2; mi++) {
            #pragma unroll
            for (int j = 0; j < 2; j++) {
                int c = col0 + wn + j * 8 + 2 * tig;
                float bb1x = eb1[e*H_ + c], bb1y = eb1[e*H_ + c + 1];
                float bb2x = eb2[e*H_ + c], bb2y = eb2[e*H_ + c + 1];
                #pragma unroll
                for (int half = 0; half < 2; half++) {
                    int li  = wm + mi * 16 + grp + half * 8;
                    int idx = i0 + li;
                    if (idx < cnt) {
                        int m = sM[li];
                        float h1x = acc1[mi][j][half*2+0] + bb1x;
                        float h1y = acc1[mi][j][half*2+1] + bb1y;
                        float h2x = acc2[mi][j][half*2+0] + bb2x;
                        float h2y = acc2[mi][j][half*2+1] + bb2y;
                        float2 o;
                        o.x = h1x * sigmoidf_(h1x) * h2x;
                        o.y = h1y * sigmoidf_(h1y) * h2y;
                        *(float2*)&g_z[(size_t)m * H_ + c] = o;
                    }
                }
            }
        }
    }
}

// ============================================================================
// K_LN: rowwise LayerNorm (width 512) for both buffers, one launch
// ============================================================================
__global__ __launch_bounds__(256) void k_ln512m(
    const float* __restrict__ g0, const float* __restrict__ b0,
    const float* __restrict__ g1, const float* __restrict__ b1)
{
    const int r = blockIdx.x;
    float* p; const float *g, *b;
    if (r < BT_) { p = g_t1 + (size_t)r * H_;         g = g0; b = b0; }
    else         { p = g_z  + (size_t)(r - BT_) * H_; g = g1; b = b1; }

    const int tid = threadIdx.x;
    float x0 = p[tid], x1 = p[tid + 256];

    __shared__ float red1[8], red2[8];
    float s = x0 + x1;
    #pragma unroll
    for (int o = 16; o; o >>= 1) s += __shfl_xor_sync(0xffffffffu, s, o);
    int w = tid >> 5, ln = tid & 31;
    if (!ln) red1[w] = s;
    __syncthreads();
    float tot = 0.f;
    #pragma unroll
    for (int i = 0; i < 8; i++) tot += red1[i];
    float mu = tot * (1.0f / (float)H_);

    float d0 = x0 - mu, d1 = x1 - mu;
    float q = d0*d0 + d1*d1;
    #pragma unroll
    for (int o = 16; o; o >>= 1) q += __shfl_xor_sync(0xffffffffu, q, o);
    if (!ln) red2[w] = q;
    __syncthreads();
    float tq = 0.f;
    #pragma unroll
    for (int i = 0; i < 8; i++) tq += red2[i];
    float rstd = rsqrtf(tq * (1.0f / (float)H_) + 1e-5f);

    p[tid]       = tf32r(d0 * rstd * g[tid]       + b[tid]);
    p[tid + 256] = tf32r(d1 * rstd * g[tid + 256] + b[tid + 256]);
}

// ============================================================================
// K_OUT2: fused output GEMMs, WRITE-DISJOINT (no recompute, no out read).
//   z == E_ : shared blocks, BM=128 BN=128: out[r] = g_t1[r]@w3r^T + b3 (ALL rows)
//   z  < E_ : expert blocks, BM=64 BN=128:  g_eo[m] = g_z[m]@ew3[e]^T + eb3
// Combine happens in k_combine (separate launch).
// ============================================================================
__global__ __launch_bounds__(256) void k_out2(
    const float* __restrict__ b3,
    const float* __restrict__ ew3, const float* __restrict__ eb3,
    float* __restrict__ out)
{
    __shared__ __align__(16) float As[ST][128][16];
    __shared__ __align__(16) float Bs[ST][128][16];
    __shared__ int sM[64];

    const int tid  = threadIdx.x;
    const int col0 = blockIdx.y * 128;
    const int wid  = tid >> 5, lane = tid & 31;
    const int grp  = lane >> 2, tig = lane & 3;
    const int wn   = (wid >> 1) * 32;
    const int lr   = tid >> 2, lc = (tid & 3) * 4;
    const int kb   = 4 * tig;
    const int NK   = H_ / 16;   // 32

    if (blockIdx.z == E_) {
        // ---- shared blocks: full shared_out GEMM, all rows ----
        const int row0 = blockIdx.x * 128;
        const int wm   = (wid & 1) * 64;

        const float* Ag0 = g_t1  + (size_t)(row0 + lr) * H_ + lc;
        const float* Ag1 = Ag0 + (size_t)64 * H_;
        const float* Bg0 = g_w3r + (size_t)(col0 + lr) * H_ + lc;
        const float* Bg1 = Bg0 + (size_t)64 * H_;

        auto issue = [&](int s, int k0) {
            cpa16(sptr(&As[s][lr]     [lc]), Ag0 + k0);
            cpa16(sptr(&As[s][lr + 64][lc]), Ag1 + k0);
            cpa16(sptr(&Bs[s][lr]     [lc]), Bg0 + k0);
            cpa16(sptr(&Bs[s][lr + 64][lc]), Bg1 + k0);
            cp_commit();
        };

        #pragma unroll
        for (int t = 0; t < ST - 1; t++) issue(t, t * 16);

        float acc[4][4][4] = {};
        for (int t0 = 0; t0 < NK; t0 += ST) {
            #pragma unroll
            for (int u = 0; u < ST; u++) {
                const int t = t0 + u;
                cp_wait<ST - 2>();
                __syncthreads();
                if (t + ST - 1 < NK) issue((u + ST - 1) % ST, (t + ST - 1) * 16);
                else cp_commit();

                float4 alo[4], ahi[4], bq[4];
                #pragma unroll
                for (int mi = 0; mi < 4; mi++) {
                    int r0 = wm + mi * 16 + grp;
                    alo[mi] = *(const float4*)&As[u][r0    ][kb];
                    ahi[mi] = *(const float4*)&As[u][r0 + 8][kb];
                }
                #pragma unroll
                for (int j = 0; j < 4; j++)
                    bq[j] = *(const float4*)&Bs[u][wn + j * 8 + grp][kb];

                unsigned a0[4][4], a1[4][4], b0[4][2], b1[4][2];
                #pragma unroll
                for (int mi = 0; mi < 4; mi++) {
                    a0[mi][0] = FU(alo[mi].x); a0[mi][1] = FU(ahi[mi].x);
                    a0[mi][2] = FU(alo[mi].y); a0[mi][3] = FU(ahi[mi].y);
                    a1[mi][0] = FU(alo[mi].z); a1[mi][1] = FU(ahi[mi].z);
                    a1[mi][2] = FU(alo[mi].w); a1[mi][3] = FU(ahi[mi].w);
                }
                #pragma unroll
                for (int j = 0; j < 4; j++) {
                    b0[j][0] = FU(bq[j].x); b0[j][1] = FU(bq[j].y);
                    b1[j][0] = FU(bq[j].z); b1[j][1] = FU(bq[j].w);
                }
                #pragma unroll
                for (int mi = 0; mi < 4; mi++)
                    #pragma unroll
                    for (int j = 0; j < 4; j++) {
                        mma8(acc[mi][j], a0[mi], b0[j]);
                        mma8(acc[mi][j], a1[mi], b1[j]);
                    }
            }
        }

        #pragma unroll
        for (int mi = 0; mi < 4; mi++) {
            #pragma unroll
            for (int j = 0; j < 4; j++) {
                int r = row0 + wm + mi * 16 + grp;
                int c = col0 + wn + j * 8 + 2 * tig;
                float bx = b3[c], by = b3[c + 1];
                #pragma unroll
                for (int half = 0; half < 2; half++) {
                    int rr = r + half * 8;
                    float2 o;
                    o.x = acc[mi][j][half*2+0] + bx;
                    o.y = acc[mi][j][half*2+1] + by;
                    *(float2*)&out[(size_t)rr * D_ + c] = o;
                }
            }
        }
    } else {
        // ---- expert blocks: write raw expert output to g_eo ----
        const int e = blockIdx.z;
        const int cnt = g_cnt[e];
        const int i0 = blockIdx.x * 64;
        if (i0 >= cnt) return;

        const int wm = (wid & 1) * 32;

        if (tid < 64) {
            int idx = i0 + tid; if (idx > cnt - 1) idx = cnt - 1;
            sM[tid] = g_perm[e * M_ + idx];
        }
        __syncthreads();

        const float* Ag  = g_z + (size_t)sM[lr] * H_ + lc;
        const float* Bg0 = ew3 + (size_t)e * D_ * H_ + (size_t)(col0 + lr) * H_ + lc;
        const float* Bg1 = Bg0 + (size_t)64 * H_;

        auto issue = [&](int s, int k0) {
            cpa16(sptr(&As[s][lr]     [lc]), Ag  + k0);
            cpa16(sptr(&Bs[s][lr]     [lc]), Bg0 + k0);
            cpa16(sptr(&Bs[s][lr + 64][lc]), Bg1 + k0);
            cp_commit();
        };

        #pragma unroll
        for (int t = 0; t < ST - 1; t++) issue(t, t * 16);

        float acc[2][4][4] = {};
        for (int t0 = 0; t0 < NK; t0 += ST) {
            #pragma unroll
            for (int u = 0; u < ST; u++) {
                const int t = t0 + u;
                cp_wait<ST - 2>();
                __syncthreads();
                if (t + ST - 1 < NK) issue((u + ST - 1) % ST, (t + ST - 1) * 16);
                else cp_commit();

                unsigned a0[2][4], a1[2][4];
                #pragma unroll
                for (int mi = 0; mi < 2; mi++) {
                    int r0 = wm + mi * 16 + grp;
                    float4 lo = *(const float4*)&As[u][r0    ][kb];
                    float4 hi = *(const float4*)&As[u][r0 + 8][kb];
                    a0[mi][0] = FU(lo.x); a0[mi][1] = FU(hi.x);
                    a0[mi][2] = FU(lo.y); a0[mi][3] = FU(hi.y);
                    a1[mi][0] = FU(lo.z); a1[mi][1] = FU(hi.z);
                    a1[mi][2] = FU(lo.w); a1[mi][3] = FU(hi.w);
                }
                unsigned b0[4][2], b1[4][2];
                #pragma unroll
                for (int j = 0; j < 4; j++) {
                    float4 bq = *(const float4*)&Bs[u][wn + j * 8 + grp][kb];
                    b0[j][0] = tf32u(bq.x); b0[j][1] = tf32u(bq.y);
                    b1[j][0] = tf32u(bq.z); b1[j][1] = tf32u(bq.w);
                }
                #pragma unroll
                for (int mi = 0; mi < 2; mi++)
                    #pragma unroll
                    for (int j = 0; j < 4; j++) {
                        mma8(acc[mi][j], a0[mi], b0[j]);
                        mma8(acc[mi][j], a1[mi], b1[j]);
                    }
            }
        }

        #pragma unroll
        for (int mi = 0; mi < 2; mi++) {
            #pragma unroll
            for (int half = 0; half < 2; half++) {
                int li  = wm + mi * 16 + grp + half * 8;
                int idx = i0 + li;
                if (idx < cnt) {
                    int m = sM[li];
                    #pragma unroll
                    for (int j = 0; j < 4; j++) {
                        int c = col0 + wn + j * 8 + 2 * tig;
                        float2 o;
                        o.x = acc[mi][j][half*2+0] + eb3[e*D_ + c];
                        o.y = acc[mi][j][half*2+1] + eb3[e*D_ + c + 1];
                        *(float2*)&g_eo[(size_t)m * D_ + c] = o;
                    }
                }
            }
        }
    }
}

// ============================================================================
// K_COMBINE: out[row] = wsh*out[row] + wex*g_eo[m]   (MoE rows only)
// M_*D_/4 float4 elements -> 2048 blocks x 256 threads
// ============================================================================
__global__ __launch_bounds__(256) void k_combine(float* __restrict__ out) {
    int i = blockIdx.x * 256 + threadIdx.x;    // < M_*D_/4
    int m = i >> 8;                             // D_/4 = 256 float4 per row
    int c4 = i & 255;
    int row = g_rowi[m];
    float wsh = g_sw[m], wex = g_ew[m];
    float4 eo = ((const float4*)g_eo)[i];
    size_t o = (size_t)row * (D_ / 4) + c4;
    float4 cur = ((float4*)out)[o];
    cur.x = wsh * cur.x + wex * eo.x;
    cur.y = wsh * cur.y + wex * eo.y;
    cur.z = wsh * cur.z + wex * eo.z;
    cur.w = wsh * cur.w + wex * eo.w;
    ((float4*)out)[o] = cur;
}

// ---------------- launch ----------------------------------------------------
extern "C" void kernel_launch(void* const* d_in, const int* in_sizes, int n_in,
                              void* d_out, int out_size)
{
    const float* x      = (const float*)d_in[0];
    const int*   ib     = (const int*)  d_in[1];
    const int*   it     = (const int*)  d_in[2];
    const float* sw1    = (const float*)d_in[3];
    const float* sb1    = (const float*)d_in[4];
    const float* sw2    = (const float*)d_in[5];
    const float* sb2    = (const float*)d_in[6];
    const float* sw3    = (const float*)d_in[7];
    const float* sb3    = (const float*)d_in[8];
    const float* slng   = (const float*)d_in[9];
    const float* slnb   = (const float*)d_in[10];
    const float* sgw    = (const float*)d_in[11];
    const float* sgb    = (const float*)d_in[12];
    const float* egw    = (const float*)d_in[13];
    const float* egb    = (const float*)d_in[14];
    const float* ebias  = (const float*)d_in[15];
    const float* ew1    = (const float*)d_in[16];
    const float* eb1    = (const float*)d_in[17];
    const float* ew2    = (const float*)d_in[18];
    const float* eb2    = (const float*)d_in[19];
    const float* ew3    = (const float*)d_in[20];
    const float* eb3    = (const float*)d_in[21];
    const float* selg   = (const float*)d_in[22];
    const float* selb   = (const float*)d_in[23];
    float* out = (float*)d_out;

    k_round_all<<<(BT_ * D_ / 4) / 256 + (H_ * D_ / 4) / 256, 256>>>(
        (const float4*)x, (const float4*)sw1,
        (const float4*)sw2, (const float4*)sw3);
    k_gate<<<M_, 256>>>(x, ib, it, sgw, sgb, egw, egb, ebias);
    k_mlp1<<<dim3(32, 8, E_ + 1), 256>>>(sb1, sb2, ew1, eb1, ew2, eb2);
    k_ln512m<<<BT_ + M_, 256>>>(slng, slnb, selg, selb);
    k_out2<<<dim3(32, D_ / 128, E_ + 1), 256>>>(sb3, ew3, eb3, out);
    k_combine<<<(M_ * D_ / 4) / 256, 256>>>(out);
}

// round 15
// speedup vs baseline: 1.1325x; 1.0290x over previous
#include <cuda_runtime.h>
#include <stdint.h>
#include <math.h>

#define B_  2
#define T_  2048
#define D_  1024
#define E_  8
#define H_  512
#define M_  2048
#define BT_ 4096
#define ST  4   // cp.async pipeline stages

// ---------------- scratch (device globals; no runtime allocation) ----------
// NOTE: g_cnt starts zeroed (module load) and is re-zeroed at the END of
// k_combine each launch, so every kernel_launch entry sees g_cnt == 0.
__device__ __align__(16) float g_xr [(size_t)BT_ * D_];  // tf32-rounded x
__device__ __align__(16) float g_w1r[(size_t)H_ * D_];   // tf32-rounded sw1
__device__ __align__(16) float g_w2r[(size_t)H_ * D_];   // tf32-rounded sw2
__device__ __align__(16) float g_w3r[(size_t)D_ * H_];   // tf32-rounded sw3
__device__ __align__(16) float g_t1[(size_t)BT_ * H_];
__device__ __align__(16) float g_z [(size_t)M_  * H_];
__device__ __align__(16) float g_eo[(size_t)M_  * D_];   // expert out (pre-combine)
__device__ int   g_rowi[M_];
__device__ float g_sw[M_];
__device__ float g_ew[M_];
__device__ int   g_cnt[E_];
__device__ int   g_perm[E_ * M_];

__device__ __forceinline__ float sigmoidf_(float v) { return 1.0f / (1.0f + expf(-v)); }

__device__ __forceinline__ float tf32r(float v) {
    unsigned u; asm("cvt.rna.tf32.f32 %0, %1;" : "=r"(u) : "f"(v));
    return __uint_as_float(u);
}
__device__ __forceinline__ unsigned tf32u(float v) {
    unsigned u; asm("cvt.rna.tf32.f32 %0, %1;" : "=r"(u) : "f"(v));
    return u;
}
#define FU(x) __float_as_uint(x)

__device__ __forceinline__ void mma8(float* c, const unsigned* a, const unsigned* b) {
    asm volatile(
        "mma.sync.aligned.m16n8k8.row.col.f32.tf32.tf32.f32 "
        "{%0,%1,%2,%3}, {%4,%5,%6,%7}, {%8,%9}, {%0,%1,%2,%3};"
        : "+f"(c[0]), "+f"(c[1]), "+f"(c[2]), "+f"(c[3])
        : "r"(a[0]), "r"(a[1]), "r"(a[2]), "r"(a[3]), "r"(b[0]), "r"(b[1]));
}

__device__ __forceinline__ void cpa16(unsigned s, const void* g) {
    asm volatile("cp.async.cg.shared.global [%0], [%1], 16;" :: "r"(s), "l"(g));
}
__device__ __forceinline__ void cp_commit() { asm volatile("cp.async.commit_group;"); }
template<int N> __device__ __forceinline__ void cp_wait() {
    asm volatile("cp.async.wait_group %0;" :: "n"(N));
}
__device__ __forceinline__ unsigned sptr(const void* p) {
    return (unsigned)__cvta_generic_to_shared(p);
}

// ============================================================================
// K0: round x + shared weights + GATING, one launch.
//   blocks [0, 4096)      -> round x (BT*D/4 float4)
//   blocks [4096, 4608)   -> round w1/w2/w3
//   blocks [4608, 6656)   -> gate token m = bx - 4608 (reads RAW x)
// g_cnt is guaranteed zero on entry (see note at globals).
// ============================================================================
#define RX_BLK ((BT_ * D_ / 4) / 256)   // 4096
#define RW_BLK ((H_ * D_ / 4) / 256)    // 512

__global__ __launch_bounds__(256) void k_round_gate(
    const float4* __restrict__ x4,
    const float4* __restrict__ w1, const float4* __restrict__ w2,
    const float4* __restrict__ w3,
    const int* __restrict__ ib, const int* __restrict__ it,
    const float* __restrict__ sgw, const float* __restrict__ sgb,
    const float* __restrict__ egw, const float* __restrict__ egb,
    const float* __restrict__ ebias)
{
    const int bx = blockIdx.x;
    const int tid = threadIdx.x;
    if (bx < RX_BLK) {
        int i = bx * 256 + tid;
        float4 v = x4[i];
        float4 o;
        o.x = tf32r(v.x); o.y = tf32r(v.y); o.z = tf32r(v.z); o.w = tf32r(v.w);
        ((float4*)g_xr)[i] = o;
    } else if (bx < RX_BLK + RW_BLK) {
        int i = (bx - RX_BLK) * 256 + tid;
        float4 a = w1[i], b = w2[i], c = w3[i];
        float4 oa, ob, oc;
        oa.x = tf32r(a.x); oa.y = tf32r(a.y); oa.z = tf32r(a.z); oa.w = tf32r(a.w);
        ob.x = tf32r(b.x); ob.y = tf32r(b.y); ob.z = tf32r(b.z); ob.w = tf32r(b.w);
        oc.x = tf32r(c.x); oc.y = tf32r(c.y); oc.z = tf32r(c.z); oc.w = tf32r(c.w);
        ((float4*)g_w1r)[i] = oa;
        ((float4*)g_w2r)[i] = ob;
        ((float4*)g_w3r)[i] = oc;
    } else {
        const int m = bx - (RX_BLK + RW_BLK);
        const int row = ib[m] * T_ + it[m];
        const float* xr = (const float*)x4 + (size_t)row * D_;

        float acc[9] = {};
        for (int d = tid; d < D_; d += 256) {
            float xv = xr[d];
            acc[0] = fmaf(xv, sgw[d], acc[0]);
            #pragma unroll
            for (int e = 0; e < E_; e++) acc[1+e] = fmaf(xv, egw[e*D_ + d], acc[1+e]);
        }
        #pragma unroll
        for (int q = 0; q < 9; q++)
            #pragma unroll
            for (int o = 16; o; o >>= 1) acc[q] += __shfl_xor_sync(0xffffffffu, acc[q], o);

        __shared__ float red[8][9];
        int w = tid >> 5, ln = tid & 31;
        if (!ln) {
            #pragma unroll
            for (int q = 0; q < 9; q++) red[w][q] = acc[q];
        }
        __syncthreads();
        if (tid == 0) {
            float dots[9];
            #pragma unroll
            for (int q = 0; q < 9; q++) {
                float s = 0.f;
                #pragma unroll
                for (int ww = 0; ww < 8; ww++) s += red[ww][q];
                dots[q] = s;
            }
            float ss = sigmoidf_(dots[0] + sgb[0]);
            float es[E_];
            float best = -1e30f; int bi = 0;
            #pragma unroll
            for (int e = 0; e < E_; e++) {
                es[e] = sigmoidf_(dots[1+e] + egb[e]);
                float sc = es[e] + ebias[e];
                if (sc > best) { best = sc; bi = e; }
            }
            float ts  = es[bi];
            g_rowi[m] = row;
            g_sw[m] = sigmoidf_(ss - ts);
            g_ew[m] = sigmoidf_(ts - ss);
            int pos = atomicAdd(&g_cnt[bi], 1);
            g_perm[bi * M_ + pos] = m;
        }
    }
}

// ============================================================================
// K_MLP1: fused first-layer dual GEMMs, phase-unrolled main loop.
//   z == E_ : shared branch, BM=128 (pre-rounded weights, no cvt)
//   z  < E_ : expert branch, BM=64 (cvt weights inline)
// ============================================================================
__global__ __launch_bounds__(256) void k_mlp1(
    const float* __restrict__ b1,  const float* __restrict__ b2,
    const float* __restrict__ ew1, const float* __restrict__ eb1,
    const float* __restrict__ ew2, const float* __restrict__ eb2)
{
    __shared__ __align__(16) float As [ST][128][16];
    __shared__ __align__(16) float B1s[ST][64][16];
    __shared__ __align__(16) float B2s[ST][64][16];
    __shared__ int sM[64], sR[64];

    const int tid  = threadIdx.x;
    const int col0 = blockIdx.y * 64;
    const int wid  = tid >> 5, lane = tid & 31;
    const int grp  = lane >> 2, tig = lane & 3;
    const int wn   = (wid >> 1) * 16;
    const int lr   = tid >> 2, lc = (tid & 3) * 4;
    const int kb   = 4 * tig;
    const int NK   = D_ / 16;   // 64, multiple of ST

    if (blockIdx.z == E_) {
        const int row0 = blockIdx.x * 128;
        const int wm   = (wid & 1) * 64;

        const float* Ag0 = g_xr  + (size_t)(row0 + lr) * D_ + lc;
        const float* Ag1 = Ag0 + (size_t)64 * D_;
        const float* B1g = g_w1r + (size_t)(col0 + lr) * D_ + lc;
        const float* B2g = g_w2r + (size_t)(col0 + lr) * D_ + lc;

        auto issue = [&](int s, int k0) {
            cpa16(sptr(&As [s][lr]     [lc]), Ag0 + k0);
            cpa16(sptr(&As [s][lr + 64][lc]), Ag1 + k0);
            cpa16(sptr(&B1s[s][lr]     [lc]), B1g + k0);
            cpa16(sptr(&B2s[s][lr]     [lc]), B2g + k0);
            cp_commit();
        };

        #pragma unroll
        for (int t = 0; t < ST - 1; t++) issue(t, t * 16);

        float acc1[4][2][4] = {}, acc2[4][2][4] = {};
        for (int t0 = 0; t0 < NK; t0 += ST) {
            #pragma unroll
            for (int u = 0; u < ST; u++) {
                const int t = t0 + u;
                cp_wait<ST - 2>();
                __syncthreads();
                if (t + ST - 1 < NK) issue((u + ST - 1) % ST, (t + ST - 1) * 16);
                else cp_commit();

                float4 alo[4], ahi[4], uu[2], vv[2];
                #pragma unroll
                for (int mi = 0; mi < 4; mi++) {
                    int r0 = wm + mi * 16 + grp;
                    alo[mi] = *(const float4*)&As[u][r0    ][kb];
                    ahi[mi] = *(const float4*)&As[u][r0 + 8][kb];
                }
                #pragma unroll
                for (int j = 0; j < 2; j++) {
                    int n = wn + j * 8 + grp;
                    uu[j] = *(const float4*)&B1s[u][n][kb];
                    vv[j] = *(const float4*)&B2s[u][n][kb];
                }
                unsigned a0[4][4], a1[4][4], bu0[2][2], bu1[2][2], bv0[2][2], bv1[2][2];
                #pragma unroll
                for (int mi = 0; mi < 4; mi++) {
                    a0[mi][0] = FU(alo[mi].x); a0[mi][1] = FU(ahi[mi].x);
                    a0[mi][2] = FU(alo[mi].y); a0[mi][3] = FU(ahi[mi].y);
                    a1[mi][0] = FU(alo[mi].z); a1[mi][1] = FU(ahi[mi].z);
                    a1[mi][2] = FU(alo[mi].w); a1[mi][3] = FU(ahi[mi].w);
                }
                #pragma unroll
                for (int j = 0; j < 2; j++) {
                    bu0[j][0] = FU(uu[j].x); bu0[j][1] = FU(uu[j].y);
                    bu1[j][0] = FU(uu[j].z); bu1[j][1] = FU(uu[j].w);
                    bv0[j][0] = FU(vv[j].x); bv0[j][1] = FU(vv[j].y);
                    bv1[j][0] = FU(vv[j].z); bv1[j][1] = FU(vv[j].w);
                }
                #pragma unroll
                for (int mi = 0; mi < 4; mi++)
                    #pragma unroll
                    for (int j = 0; j < 2; j++) {
                        mma8(acc1[mi][j], a0[mi], bu0[j]);
                        mma8(acc1[mi][j], a1[mi], bu1[j]);
                        mma8(acc2[mi][j], a0[mi], bv0[j]);
                        mma8(acc2[mi][j], a1[mi], bv1[j]);
                    }
            }
        }

        #pragma unroll
        for (int mi = 0; mi < 4; mi++) {
            #pragma unroll
            for (int j = 0; j < 2; j++) {
                int r = row0 + wm + mi * 16 + grp;
                int c = col0 + wn + j * 8 + 2 * tig;
                float bb1x = b1[c], bb1y = b1[c + 1];
                float bb2x = b2[c], bb2y = b2[c + 1];
                #pragma unroll
                for (int half = 0; half < 2; half++) {
                    int rr = r + half * 8;
                    float h1x = acc1[mi][j][half*2+0] + bb1x;
                    float h1y = acc1[mi][j][half*2+1] + bb1y;
                    float h2x = acc2[mi][j][half*2+0] + bb2x;
                    float h2y = acc2[mi][j][half*2+1] + bb2y;
                    float2 o;
                    o.x = h1x * sigmoidf_(h1x) * h2x;
                    o.y = h1y * sigmoidf_(h1y) * h2y;
                    *(float2*)&g_t1[(size_t)rr * H_ + c] = o;
                }
            }
        }
    } else {
        const int e = blockIdx.z;
        const int cnt = g_cnt[e];
        const int i0 = blockIdx.x * 64;
        if (i0 >= cnt) return;

        const int wm = (wid & 1) * 32;

        if (tid < 64) {
            int idx = i0 + tid; if (idx > cnt - 1) idx = cnt - 1;
            int m = g_perm[e * M_ + idx];
            sM[tid] = m; sR[tid] = g_rowi[m];
        }
        __syncthreads();

        const float* Ag  = g_xr + (size_t)sR[lr] * D_ + lc;
        const float* B1g = ew1 + (size_t)e * H_ * D_ + (size_t)(col0 + lr) * D_ + lc;
        const float* B2g = ew2 + (size_t)e * H_ * D_ + (size_t)(col0 + lr) * D_ + lc;

        auto issue = [&](int s, int k0) {
            cpa16(sptr(&As [s][lr][lc]), Ag  + k0);
            cpa16(sptr(&B1s[s][lr][lc]), B1g + k0);
            cpa16(sptr(&B2s[s][lr][lc]), B2g + k0);
            cp_commit();
        };

        #pragma unroll
        for (int t = 0; t < ST - 1; t++) issue(t, t * 16);

        float acc1[2][2][4] = {}, acc2[2][2][4] = {};
        for (int t0 = 0; t0 < NK; t0 += ST) {
            #pragma unroll
            for (int u = 0; u < ST; u++) {
                const int t = t0 + u;
                cp_wait<ST - 2>();
                __syncthreads();
                if (t + ST - 1 < NK) issue((u + ST - 1) % ST, (t + ST - 1) * 16);
                else cp_commit();

                unsigned a0[2][4], a1[2][4];
                #pragma unroll
                for (int mi = 0; mi < 2; mi++) {
                    int r0 = wm + mi * 16 + grp;
                    float4 lo = *(const float4*)&As[u][r0    ][kb];
                    float4 hi = *(const float4*)&As[u][r0 + 8][kb];
                    a0[mi][0] = FU(lo.x); a0[mi][1] = FU(hi.x);
                    a0[mi][2] = FU(lo.y); a0[mi][3] = FU(hi.y);
                    a1[mi][0] = FU(lo.z); a1[mi][1] = FU(hi.z);
                    a1[mi][2] = FU(lo.w); a1[mi][3] = FU(hi.w);
                }
                unsigned bu0[2][2], bu1[2][2], bv0[2][2], bv1[2][2];
                #pragma unroll
                for (int j = 0; j < 2; j++) {
                    int n = wn + j * 8 + grp;
                    float4 uu = *(const float4*)&B1s[u][n][kb];
                    float4 vv = *(const float4*)&B2s[u][n][kb];
                    bu0[j][0] = tf32u(uu.x); bu0[j][1] = tf32u(uu.y);
                    bu1[j][0] = tf32u(uu.z); bu1[j][1] = tf32u(uu.w);
                    bv0[j][0] = tf32u(vv.x); bv0[j][1] = tf32u(vv.y);
                    bv1[j][0] = tf32u(vv.z); bv1[j][1] = tf32u(vv.w);
                }
                #pragma unroll
                for (int mi = 0; mi < 2; mi++)
                    #pragma unroll
                    for (int j = 0; j < 2; j++) {
                        mma8(acc1[mi][j], a0[mi], bu0[j]);
                        mma8(acc1[mi][j], a1[mi], bu1[j]);
                        mma8(acc2[mi][j], a0[mi], bv0[j]);
                        mma8(acc2[mi][j], a1[mi], bv1[j]);
                    }
            }
        }

        #pragma unroll
        for (int mi = 0; mi < 2; mi++) {
            #pragma unroll
            for (int j = 0; j < 2; j++) {
                int c = col0 + wn + j * 8 + 2 * tig;
                float bb1x = eb1[e*H_ + c], bb1y = eb1[e*H_ + c + 1];
                float bb2x = eb2[e*H_ + c], bb2y = eb2[e*H_ + c + 1];
                #pragma unroll
                for (int half = 0; half < 2; half++) {
                    int li  = wm + mi * 16 + grp + half * 8;
                    int idx = i0 + li;
                    if (idx < cnt) {
                        int m = sM[li];
                        float h1x = acc1[mi][j][half*2+0] + bb1x;
                        float h1y = acc1[mi][j][half*2+1] + bb1y;
                        float h2x = acc2[mi][j][half*2+0] + bb2x;
                        float h2y = acc2[mi][j][half*2+1] + bb2y;
                        float2 o;
                        o.x = h1x * sigmoidf_(h1x) * h2x;
                        o.y = h1y * sigmoidf_(h1y) * h2y;
                        *(float2*)&g_z[(size_t)m * H_ + c] = o;
                    }
                }
            }
        }
    }
}

// ============================================================================
// K_LN: rowwise LayerNorm (width 512), vectorized float4, 128 thr/row.
//   blocks [0, BT_)      -> g_t1 rows with s_ln
//   blocks [BT_, BT_+M_) -> g_z rows with sel_ln
// ============================================================================
__global__ __launch_bounds__(128) void k_ln512v(
    const float* __restrict__ g0, const float* __restrict__ b0,
    const float* __restrict__ g1, const float* __restrict__ b1)
{
    const int r = blockIdx.x;
    float* p; const float *g, *b;
    if (r < BT_) { p = g_t1 + (size_t)r * H_;         g = g0; b = b0; }
    else         { p = g_z  + (size_t)(r - BT_) * H_; g = g1; b = b1; }

    const int tid = threadIdx.x;   // 0..127, one float4 each (512 floats/row)
    float4 v = ((const float4*)p)[tid];

    __shared__ float red1[4], red2[4];
    float s = v.x + v.y + v.z + v.w;
    #pragma unroll
    for (int o = 16; o; o >>= 1) s += __shfl_xor_sync(0xffffffffu, s, o);
    int w = tid >> 5, ln = tid & 31;
    if (!ln) red1[w] = s;
    __syncthreads();
    float mu = (red1[0] + red1[1] + red1[2] + red1[3]) * (1.0f / (float)H_);

    float dx = v.x - mu, dy = v.y - mu, dz = v.z - mu, dw = v.w - mu;
    float q = dx*dx + dy*dy + dz*dz + dw*dw;
    #pragma unroll
    for (int o = 16; o; o >>= 1) q += __shfl_xor_sync(0xffffffffu, q, o);
    if (!ln) red2[w] = q;
    __syncthreads();
    float rstd = rsqrtf((red2[0] + red2[1] + red2[2] + red2[3]) * (1.0f / (float)H_)
                        + 1e-5f);

    float4 gv = ((const float4*)g)[tid];
    float4 bv = ((const float4*)b)[tid];
    float4 o;
    o.x = tf32r(dx * rstd * gv.x + bv.x);
    o.y = tf32r(dy * rstd * gv.y + bv.y);
    o.z = tf32r(dz * rstd * gv.z + bv.z);
    o.w = tf32r(dw * rstd * gv.w + bv.w);
    ((float4*)p)[tid] = o;
}

// ============================================================================
// K_OUT2: fused output GEMMs, WRITE-DISJOINT (no recompute, no out read).
//   z == E_ : shared blocks, BM=128 BN=128: out[r] = g_t1[r]@w3r^T + b3 (ALL rows)
//   z  < E_ : expert blocks, BM=64 BN=128:  g_eo[m] = g_z[m]@ew3[e]^T + eb3
// ============================================================================
__global__ __launch_bounds__(256) void k_out2(
    const float* __restrict__ b3,
    const float* __restrict__ ew3, const float* __restrict__ eb3,
    float* __restrict__ out)
{
    __shared__ __align__(16) float As[ST][128][16];
    __shared__ __align__(16) float Bs[ST][128][16];
    __shared__ int sM[64];

    const int tid  = threadIdx.x;
    const int col0 = blockIdx.y * 128;
    const int wid  = tid >> 5, lane = tid & 31;
    const int grp  = lane >> 2, tig = lane & 3;
    const int wn   = (wid >> 1) * 32;
    const int lr   = tid >> 2, lc = (tid & 3) * 4;
    const int kb   = 4 * tig;
    const int NK   = H_ / 16;   // 32

    if (blockIdx.z == E_) {
        const int row0 = blockIdx.x * 128;
        const int wm   = (wid & 1) * 64;

        const float* Ag0 = g_t1  + (size_t)(row0 + lr) * H_ + lc;
        const float* Ag1 = Ag0 + (size_t)64 * H_;
        const float* Bg0 = g_w3r + (size_t)(col0 + lr) * H_ + lc;
        const float* Bg1 = Bg0 + (size_t)64 * H_;

        auto issue = [&](int s, int k0) {
            cpa16(sptr(&As[s][lr]     [lc]), Ag0 + k0);
            cpa16(sptr(&As[s][lr + 64][lc]), Ag1 + k0);
            cpa16(sptr(&Bs[s][lr]     [lc]), Bg0 + k0);
            cpa16(sptr(&Bs[s][lr + 64][lc]), Bg1 + k0);
            cp_commit();
        };

        #pragma unroll
        for (int t = 0; t < ST - 1; t++) issue(t, t * 16);

        float acc[4][4][4] = {};
        for (int t0 = 0; t0 < NK; t0 += ST) {
            #pragma unroll
            for (int u = 0; u < ST; u++) {
                const int t = t0 + u;
                cp_wait<ST - 2>();
                __syncthreads();
                if (t + ST - 1 < NK) issue((u + ST - 1) % ST, (t + ST - 1) * 16);
                else cp_commit();

                float4 alo[4], ahi[4], bq[4];
                #pragma unroll
                for (int mi = 0; mi < 4; mi++) {
                    int r0 = wm + mi * 16 + grp;
                    alo[mi] = *(const float4*)&As[u][r0    ][kb];
                    ahi[mi] = *(const float4*)&As[u][r0 + 8][kb];
                }
                #pragma unroll
                for (int j = 0; j < 4; j++)
                    bq[j] = *(const float4*)&Bs[u][wn + j * 8 + grp][kb];

                unsigned a0[4][4], a1[4][4], b0[4][2], b1[4][2];
                #pragma unroll
                for (int mi = 0; mi < 4; mi++) {
                    a0[mi][0] = FU(alo[mi].x); a0[mi][1] = FU(ahi[mi].x);
                    a0[mi][2] = FU(alo[mi].y); a0[mi][3] = FU(ahi[mi].y);
                    a1[mi][0] = FU(alo[mi].z); a1[mi][1] = FU(ahi[mi].z);
                    a1[mi][2] = FU(alo[mi].w); a1[mi][3] = FU(ahi[mi].w);
                }
                #pragma unroll
                for (int j = 0; j < 4; j++) {
                    b0[j][0] = FU(bq[j].x); b0[j][1] = FU(bq[j].y);
                    b1[j][0] = FU(bq[j].z); b1[j][1] = FU(bq[j].w);
                }
                #pragma unroll
                for (int mi = 0; mi < 4; mi++)
                    #pragma unroll
                    for (int j = 0; j < 4; j++) {
                        mma8(acc[mi][j], a0[mi], b0[j]);
                        mma8(acc[mi][j], a1[mi], b1[j]);
                    }
            }
        }

        #pragma unroll
        for (int mi = 0; mi < 4; mi++) {
            #pragma unroll
            for (int j = 0; j < 4; j++) {
                int r = row0 + wm + mi * 16 + grp;
                int c = col0 + wn + j * 8 + 2 * tig;
                float bx = b3[c], by = b3[c + 1];
                #pragma unroll
                for (int half = 0; half < 2; half++) {
                    int rr = r + half * 8;
                    float2 o;
                    o.x = acc[mi][j][half*2+0] + bx;
                    o.y = acc[mi][j][half*2+1] + by;
                    *(float2*)&out[(size_t)rr * D_ + c] = o;
                }
            }
        }
    } else {
        const int e = blockIdx.z;
        const int cnt = g_cnt[e];
        const int i0 = blockIdx.x * 64;
        if (i0 >= cnt) return;

        const int wm = (wid & 1) * 32;

        if (tid < 64) {
            int idx = i0 + tid; if (idx > cnt - 1) idx = cnt - 1;
            sM[tid] = g_perm[e * M_ + idx];
        }
        __syncthreads();

        const float* Ag  = g_z + (size_t)sM[lr] * H_ + lc;
        const float* Bg0 = ew3 + (size_t)e * D_ * H_ + (size_t)(col0 + lr) * H_ + lc;
        const float* Bg1 = Bg0 + (size_t)64 * H_;

        auto issue = [&](int s, int k0) {
            cpa16(sptr(&As[s][lr]     [lc]), Ag  + k0);
            cpa16(sptr(&Bs[s][lr]     [lc]), Bg0 + k0);
            cpa16(sptr(&Bs[s][lr + 64][lc]), Bg1 + k0);
            cp_commit();
        };

        #pragma unroll
        for (int t = 0; t < ST - 1; t++) issue(t, t * 16);

        float acc[2][4][4] = {};
        for (int t0 = 0; t0 < NK; t0 += ST) {
            #pragma unroll
            for (int u = 0; u < ST; u++) {
                const int t = t0 + u;
                cp_wait<ST - 2>();
                __syncthreads();
                if (t + ST - 1 < NK) issue((u + ST - 1) % ST, (t + ST - 1) * 16);
                else cp_commit();

                unsigned a0[2][4], a1[2][4];
                #pragma unroll
                for (int mi = 0; mi < 2; mi++) {
                    int r0 = wm + mi * 16 + grp;
                    float4 lo = *(const float4*)&As[u][r0    ][kb];
                    float4 hi = *(const float4*)&As[u][r0 + 8][kb];
                    a0[mi][0] = FU(lo.x); a0[mi][1] = FU(hi.x);
                    a0[mi][2] = FU(lo.y); a0[mi][3] = FU(hi.y);
                    a1[mi][0] = FU(lo.z); a1[mi][1] = FU(hi.z);
                    a1[mi][2] = FU(lo.w); a1[mi][3] = FU(hi.w);
                }
                unsigned b0[4][2], b1[4][2];
                #pragma unroll
                for (int j = 0; j < 4; j++) {
                    float4 bq = *(const float4*)&Bs[u][wn + j * 8 + grp][kb];
                    b0[j][0] = tf32u(bq.x); b0[j][1] = tf32u(bq.y);
                    b1[j][0] = tf32u(bq.z); b1[j][1] = tf32u(bq.w);
                }
                #pragma unroll
                for (int mi = 0; mi < 2; mi++)
                    #pragma unroll
                    for (int j = 0; j < 4; j++) {
                        mma8(acc[mi][j], a0[mi], b0[j]);
                        mma8(acc[mi][j], a1[mi], b1[j]);
                    }
            }
        }

        #pragma unroll
        for (int mi = 0; mi < 2; mi++) {
            #pragma unroll
            for (int half = 0; half < 2; half++) {
                int li  = wm + mi * 16 + grp + half * 8;
                int idx = i0 + li;
                if (idx < cnt) {
                    int m = sM[li];
                    #pragma unroll
                    for (int j = 0; j < 4; j++) {
                        int c = col0 + wn + j * 8 + 2 * tig;
                        float2 o;
                        o.x = acc[mi][j][half*2+0] + eb3[e*D_ + c];
                        o.y = acc[mi][j][half*2+1] + eb3[e*D_ + c + 1];
                        *(float2*)&g_eo[(size_t)m * D_ + c] = o;
                    }
                }
            }
        }
    }
}

// ============================================================================
// K_COMBINE: out[row] = wsh*out[row] + wex*g_eo[m]; then re-zero g_cnt.
// ============================================================================
__global__ __launch_bounds__(256) void k_combine(float* __restrict__ out) {
    int i = blockIdx.x * 256 + threadIdx.x;    // < M_*D_/4
    int m = i >> 8;                             // D_/4 = 256 float4 per row
    int c4 = i & 255;
    int row = g_rowi[m];
    float wsh = g_sw[m], wex = g_ew[m];
    float4 eo = ((const float4*)g_eo)[i];
    size_t o = (size_t)row * (D_ / 4) + c4;
    float4 cur = ((float4*)out)[o];
    cur.x = wsh * cur.x + wex * eo.x;
    cur.y = wsh * cur.y + wex * eo.y;
    cur.z = wsh * cur.z + wex * eo.z;
    cur.w = wsh * cur.w + wex * eo.w;
    ((float4*)out)[o] = cur;
    if (blockIdx.x == 0 && threadIdx.x < E_) g_cnt[threadIdx.x] = 0;
}

// ---------------- launch ----------------------------------------------------
extern "C" void kernel_launch(void* const* d_in, const int* in_sizes, int n_in,
                              void* d_out, int out_size)
{
    const float* x      = (const float*)d_in[0];
    const int*   ib     = (const int*)  d_in[1];
    const int*   it     = (const int*)  d_in[2];
    const float* sw1    = (const float*)d_in[3];
    const float* sb1    = (const float*)d_in[4];
    const float* sw2    = (const float*)d_in[5];
    const float* sb2    = (const float*)d_in[6];
    const float* sw3    = (const float*)d_in[7];
    const float* sb3    = (const float*)d_in[8];
    const float* slng   = (const float*)d_in[9];
    const float* slnb   = (const float*)d_in[10];
    const float* sgw    = (const float*)d_in[11];
    const float* sgb    = (const float*)d_in[12];
    const float* egw    = (const float*)d_in[13];
    const float* egb    = (const float*)d_in[14];
    const float* ebias  = (const float*)d_in[15];
    const float* ew1    = (const float*)d_in[16];
    const float* eb1    = (const float*)d_in[17];
    const float* ew2    = (const float*)d_in[18];
    const float* eb2    = (const float*)d_in[19];
    const float* ew3    = (const float*)d_in[20];
    const float* eb3    = (const float*)d_in[21];
    const float* selg   = (const float*)d_in[22];
    const float* selb   = (const float*)d_in[23];
    float* out = (float*)d_out;

    k_round_gate<<<RX_BLK + RW_BLK + M_, 256>>>(
        (const float4*)x, (const float4*)sw1, (const float4*)sw2,
        (const float4*)sw3, ib, it, sgw, sgb, egw, egb, ebias);
    k_mlp1<<<dim3(32, 8, E_ + 1), 256>>>(sb1, sb2, ew1, eb1, ew2, eb2);
    k_ln512v<<<BT_ + M_, 128>>>(slng, slnb, selg, selb);
    k_out2<<<dim3(32, D_ / 128, E_ + 1), 256>>>(sb3, ew3, eb3, out);
    k_combine<<<(M_ * D_ / 4) / 256, 256>>>(out);
}